// round 1
// baseline (speedup 1.0000x reference)
#include <cuda_runtime.h>
#include <cstdint>

// Problem constants (fixed by the dataset)
#define MAXN 50000
#define GG   1024
#define DD   128

// Scratch (static __device__ — no allocations allowed)
__device__ float g_hA[MAXN * DD];
__device__ float g_hB[MAXN * DD];
__device__ float g_agg[MAXN * DD];
__device__ float g_t[MAXN * 2 * DD];
__device__ float g_vn[GG * DD];
__device__ float g_gsum[GG * DD];
__device__ float g_vt[GG * 2 * DD];

// ---------------------------------------------------------------------------
// AtomEncoder: h[n,c] = sum_f atom_emb[f, x[n,f], c]
// ---------------------------------------------------------------------------
__global__ void atom_encode_k(const int* __restrict__ xa,
                              const float* __restrict__ emb,
                              float* __restrict__ h, int n) {
    int idx = blockIdx.x * blockDim.x + threadIdx.x;
    if (idx >= n * 32) return;
    int node = idx >> 5;
    int c4 = (idx & 31) << 2;
    float4 s = make_float4(0.f, 0.f, 0.f, 0.f);
#pragma unroll
    for (int f = 0; f < 9; f++) {
        int v = xa[node * 9 + f];
        float4 e = *(const float4*)(emb + (f * 100 + v) * DD + c4);
        s.x += e.x; s.y += e.y; s.z += e.z; s.w += e.w;
    }
    *(float4*)(h + node * DD + c4) = s;
}

// vn[g,c] = vn_emb0[c]
__global__ void vn_init_k(const float* __restrict__ v0, float* __restrict__ vn) {
    int idx = blockIdx.x * blockDim.x + threadIdx.x;
    if (idx >= GG * 32) return;
    int c4 = (idx & 31) << 2;
    *(float4*)(vn + idx * 4) = *(const float4*)(v0 + c4);
}

// h += vn[batch]; agg = 0; gsum = 0
__global__ void add_vn_zero_k(float* __restrict__ h, const float* __restrict__ vn,
                              const int* __restrict__ batch, float* __restrict__ agg,
                              float* __restrict__ gsum, int n) {
    int idx = blockIdx.x * blockDim.x + threadIdx.x;
    if (idx >= n * 32) return;
    int node = idx >> 5;
    int c4 = (idx & 31) << 2;
    int g = batch[node];
    float4 hv = *(float4*)(h + idx * 4);
    float4 vv = *(const float4*)(vn + g * DD + c4);
    hv.x += vv.x; hv.y += vv.y; hv.z += vv.z; hv.w += vv.w;
    *(float4*)(h + idx * 4) = hv;
    *(float4*)(agg + idx * 4) = make_float4(0.f, 0.f, 0.f, 0.f);
    if (idx < GG * 32)
        *(float4*)(gsum + idx * 4) = make_float4(0.f, 0.f, 0.f, 0.f);
}

// ---------------------------------------------------------------------------
// Edge kernel: msg = relu(h[src] + bond_e), scatter-add to agg[dst]
// Bond table for the layer (3*10*128 floats) cached in smem. Warp per edge.
// ---------------------------------------------------------------------------
__global__ void edge_k(const int* __restrict__ ei, const int* __restrict__ ea,
                       const float* __restrict__ bond, const float* __restrict__ h,
                       float* __restrict__ agg, int ecnt) {
    __shared__ __align__(16) float tbl[3 * 10 * DD];
    for (int i = threadIdx.x; i < 3 * 10 * DD; i += blockDim.x) tbl[i] = bond[i];
    __syncthreads();
    int lane = threadIdx.x & 31;
    int warp = (blockIdx.x * blockDim.x + threadIdx.x) >> 5;
    int nwarps = (gridDim.x * blockDim.x) >> 5;
    int c = lane << 2;
    for (int j = warp; j < ecnt; j += nwarps) {
        int src = ei[j];
        int dst = ei[ecnt + j];
        int a0 = ea[j * 3 + 0], a1 = ea[j * 3 + 1], a2 = ea[j * 3 + 2];
        float4 hv = *(const float4*)(h + src * DD + c);
        float4 e0 = *(const float4*)(tbl + a0 * DD + c);
        float4 e1 = *(const float4*)(tbl + 10 * DD + a1 * DD + c);
        float4 e2 = *(const float4*)(tbl + 20 * DD + a2 * DD + c);
        float x = fmaxf(hv.x + e0.x + e1.x + e2.x, 0.f);
        float y = fmaxf(hv.y + e0.y + e1.y + e2.y, 0.f);
        float z = fmaxf(hv.z + e0.z + e1.z + e2.z, 0.f);
        float w = fmaxf(hv.w + e0.w + e1.w + e2.w, 0.f);
        float* p = agg + (size_t)dst * DD + c;
        asm volatile("red.global.add.v4.f32 [%0], {%1,%2,%3,%4};"
                     :: "l"(p), "f"(x), "f"(y), "f"(z), "f"(w) : "memory");
    }
}

// gsum[batch[n]] += h[n]
__global__ void segsum_k(const float* __restrict__ h, const int* __restrict__ batch,
                         float* __restrict__ gsum, int n) {
    int idx = blockIdx.x * blockDim.x + threadIdx.x;
    if (idx >= n * 32) return;
    int node = idx >> 5;
    int c4 = (idx & 31) << 2;
    int g = batch[node];
    float4 v = *(const float4*)(h + idx * 4);
    float* p = gsum + g * DD + c4;
    asm volatile("red.global.add.v4.f32 [%0], {%1,%2,%3,%4};"
                 :: "l"(p), "f"(v.x), "f"(v.y), "f"(v.z), "f"(v.w) : "memory");
}

// ---------------------------------------------------------------------------
// Fused GEMM: C = act( bn( (al*A + A2) @ W + lin_b ) )
//   A [M,K], W [K,N] row-major. BN folded per-column:
//   out = dot*s + (lin_b - m)*s + b,  s = g * rsqrt(v + 1e-5)
//   If A2 != nullptr: operand = al*A + A2  (al = 1 + *alpha_ptr, or 1).
// Tile 128x128, BK=16, 256 threads, 8x8 per thread, packed fma.rn.f32x2.
// ---------------------------------------------------------------------------
#define BM 128
#define BN 128
#define BK 16

union F2U { float2 f2; unsigned long long u; };

__global__ void __launch_bounds__(256, 2)
gemm_fused_k(const float* __restrict__ A, const float* __restrict__ A2,
             const float* __restrict__ alpha_ptr,
             const float* __restrict__ W, const float* __restrict__ lin_b,
             const float* __restrict__ bng, const float* __restrict__ bnb,
             const float* __restrict__ bnm, const float* __restrict__ bnv,
             float* __restrict__ C, int M, int N, int K, int do_relu) {
    __shared__ float As[2][BK][BM];
    __shared__ float Bs[2][BK][BN];

    int tid = threadIdx.x;
    int bm = blockIdx.x * BM;
    int bn = blockIdx.y * BN;

    float al = 1.0f;
    if (alpha_ptr) al = 1.0f + *alpha_ptr;

    // A-load mapping: 2 float4 per thread
    int rA = tid >> 2;            // 0..63
    int kA = (tid & 3) << 2;      // 0,4,8,12
    // B-load mapping: 2 float4 per thread
    int kB = tid >> 5;            // 0..7
    int cB = (tid & 31) << 2;     // 0..124

    int tx = tid & 15;            // col group
    int ty = tid >> 4;            // row group

    unsigned long long acc[8][4];
#pragma unroll
    for (int i = 0; i < 8; i++)
#pragma unroll
        for (int j = 0; j < 4; j++) acc[i][j] = 0ull;

    int nch = K >> 4;

    float4 pa[2], pb[2];
    // load chunk 0
    {
#pragma unroll
        for (int i = 0; i < 2; i++) {
            int gr = bm + rA + i * 64;
            float4 v = make_float4(0.f, 0.f, 0.f, 0.f);
            if (gr < M) {
                v = *(const float4*)(A + (size_t)gr * K + kA);
                if (A2) {
                    float4 v2 = *(const float4*)(A2 + (size_t)gr * K + kA);
                    v.x = al * v.x + v2.x; v.y = al * v.y + v2.y;
                    v.z = al * v.z + v2.z; v.w = al * v.w + v2.w;
                }
            }
            pa[i] = v;
        }
#pragma unroll
        for (int i = 0; i < 2; i++) {
            int kk = kB + i * 8;
            pb[i] = *(const float4*)(W + (size_t)kk * N + bn + cB);
        }
#pragma unroll
        for (int i = 0; i < 2; i++) {
            int r = rA + i * 64;
            As[0][kA + 0][r] = pa[i].x;
            As[0][kA + 1][r] = pa[i].y;
            As[0][kA + 2][r] = pa[i].z;
            As[0][kA + 3][r] = pa[i].w;
            *(float4*)&Bs[0][kB + i * 8][cB] = pb[i];
        }
    }
    __syncthreads();

    for (int c = 0; c < nch; c++) {
        int cur = c & 1;
        bool has = (c + 1 < nch);
        float4 qa[2], qb[2];
        if (has) {
            int kbase = (c + 1) * BK;
#pragma unroll
            for (int i = 0; i < 2; i++) {
                int gr = bm + rA + i * 64;
                float4 v = make_float4(0.f, 0.f, 0.f, 0.f);
                if (gr < M) {
                    v = *(const float4*)(A + (size_t)gr * K + kbase + kA);
                    if (A2) {
                        float4 v2 = *(const float4*)(A2 + (size_t)gr * K + kbase + kA);
                        v.x = al * v.x + v2.x; v.y = al * v.y + v2.y;
                        v.z = al * v.z + v2.z; v.w = al * v.w + v2.w;
                    }
                }
                qa[i] = v;
            }
#pragma unroll
            for (int i = 0; i < 2; i++) {
                int kk = kB + i * 8;
                qb[i] = *(const float4*)(W + (size_t)(kbase + kk) * N + bn + cB);
            }
        }
        // compute on buffer `cur`
#pragma unroll
        for (int kk = 0; kk < BK; kk++) {
            float4 a0 = *(const float4*)&As[cur][kk][ty * 8];
            float4 a1 = *(const float4*)&As[cur][kk][ty * 8 + 4];
            unsigned long long bb[4];
            bb[0] = *(const unsigned long long*)&Bs[cur][kk][tx * 8 + 0];
            bb[1] = *(const unsigned long long*)&Bs[cur][kk][tx * 8 + 2];
            bb[2] = *(const unsigned long long*)&Bs[cur][kk][tx * 8 + 4];
            bb[3] = *(const unsigned long long*)&Bs[cur][kk][tx * 8 + 6];
            float av[8] = {a0.x, a0.y, a0.z, a0.w, a1.x, a1.y, a1.z, a1.w};
#pragma unroll
            for (int i = 0; i < 8; i++) {
                unsigned long long aa;
                unsigned int au = __float_as_uint(av[i]);
                asm("mov.b64 %0, {%1, %1};" : "=l"(aa) : "r"(au));
#pragma unroll
                for (int j = 0; j < 4; j++) {
                    asm("fma.rn.f32x2 %0, %1, %2, %0;"
                        : "+l"(acc[i][j]) : "l"(aa), "l"(bb[j]));
                }
            }
        }
        if (has) {
            int nxt = cur ^ 1;
#pragma unroll
            for (int i = 0; i < 2; i++) {
                int r = rA + i * 64;
                As[nxt][kA + 0][r] = qa[i].x;
                As[nxt][kA + 1][r] = qa[i].y;
                As[nxt][kA + 2][r] = qa[i].z;
                As[nxt][kA + 3][r] = qa[i].w;
                *(float4*)&Bs[nxt][kB + i * 8][cB] = qb[i];
            }
        }
        __syncthreads();
    }

    // Epilogue: fold BN + bias, optional relu
    float s[8], bsv[8];
#pragma unroll
    for (int j = 0; j < 8; j++) {
        int col = bn + tx * 8 + j;
        float sc = bng[col] * rsqrtf(bnv[col] + 1e-5f);
        s[j] = sc;
        bsv[j] = (lin_b[col] - bnm[col]) * sc + bnb[col];
    }
#pragma unroll
    for (int i = 0; i < 8; i++) {
        int row = bm + ty * 8 + i;
        if (row >= M) continue;
        float o[8];
#pragma unroll
        for (int j = 0; j < 4; j++) {
            F2U u; u.u = acc[i][j];
            o[2 * j + 0] = u.f2.x;
            o[2 * j + 1] = u.f2.y;
        }
#pragma unroll
        for (int j = 0; j < 8; j++) {
            float v = o[j] * s[j] + bsv[j];
            if (do_relu) v = fmaxf(v, 0.f);
            o[j] = v;
        }
        float* cp = C + (size_t)row * N + bn + tx * 8;
        *(float4*)(cp + 0) = make_float4(o[0], o[1], o[2], o[3]);
        *(float4*)(cp + 4) = make_float4(o[4], o[5], o[6], o[7]);
    }
}

// ---------------------------------------------------------------------------
// Host driver
// ---------------------------------------------------------------------------
extern "C" void kernel_launch(void* const* d_in, const int* in_sizes, int n_in,
                              void* d_out, int out_size) {
    const int*   x_atom  = (const int*)d_in[0];
    const int*   ei      = (const int*)d_in[1];
    const int*   ea      = (const int*)d_in[2];
    const int*   batch   = (const int*)d_in[3];
    const float* atomemb = (const float*)d_in[4];
    const float* vn0     = (const float*)d_in[5];
    const float* bond    = (const float*)d_in[6];
    const float* eps     = (const float*)d_in[7];
    const float* W1      = (const float*)d_in[8];
    const float* b1      = (const float*)d_in[9];
    const float* bn1g    = (const float*)d_in[10];
    const float* bn1b    = (const float*)d_in[11];
    const float* bn1m    = (const float*)d_in[12];
    const float* bn1v    = (const float*)d_in[13];
    const float* W2      = (const float*)d_in[14];
    const float* b2      = (const float*)d_in[15];
    const float* bng     = (const float*)d_in[16];
    const float* bnb     = (const float*)d_in[17];
    const float* bnm     = (const float*)d_in[18];
    const float* bnv     = (const float*)d_in[19];
    const float* vnW1    = (const float*)d_in[20];
    const float* vnb1    = (const float*)d_in[21];
    const float* vbn1g   = (const float*)d_in[22];
    const float* vbn1b   = (const float*)d_in[23];
    const float* vbn1m   = (const float*)d_in[24];
    const float* vbn1v   = (const float*)d_in[25];
    const float* vnW2    = (const float*)d_in[26];
    const float* vnb2    = (const float*)d_in[27];
    const float* vbn2g   = (const float*)d_in[28];
    const float* vbn2b   = (const float*)d_in[29];
    const float* vbn2m   = (const float*)d_in[30];
    const float* vbn2v   = (const float*)d_in[31];

    int n = in_sizes[3];          // N nodes
    int ecnt = in_sizes[1] / 2;   // E edges

    float *hA, *hB, *agg, *t, *vn, *gsum, *vt;
    cudaGetSymbolAddress((void**)&hA, g_hA);
    cudaGetSymbolAddress((void**)&hB, g_hB);
    cudaGetSymbolAddress((void**)&agg, g_agg);
    cudaGetSymbolAddress((void**)&t, g_t);
    cudaGetSymbolAddress((void**)&vn, g_vn);
    cudaGetSymbolAddress((void**)&gsum, g_gsum);
    cudaGetSymbolAddress((void**)&vt, g_vt);

    int nThreads = 256;
    int gridND = (n * 32 + nThreads - 1) / nThreads;

    atom_encode_k<<<gridND, nThreads>>>(x_atom, atomemb, hA, n);
    vn_init_k<<<(GG * 32 + nThreads - 1) / nThreads, nThreads>>>(vn0, vn);

    float* hcur = hA;
    float* hnxt = hB;
    const int L = 3;
    for (int l = 0; l < L; l++) {
        add_vn_zero_k<<<gridND, nThreads>>>(hcur, vn, batch, agg, gsum, n);
        edge_k<<<1480, nThreads>>>(ei, ea, bond + (size_t)l * 3 * 10 * DD, hcur, agg, ecnt);
        if (l < L - 1)
            segsum_k<<<gridND, nThreads>>>(hcur, batch, gsum, n);

        // GEMM1: z = (1+eps)*h + agg; t = relu(bn1(z @ W1 + b1))   [n,256]
        {
            dim3 g((n + BM - 1) / BM, 2);
            gemm_fused_k<<<g, 256>>>(hcur, agg, eps + l,
                                     W1 + (size_t)l * DD * 2 * DD, b1 + l * 2 * DD,
                                     bn1g + l * 2 * DD, bn1b + l * 2 * DD,
                                     bn1m + l * 2 * DD, bn1v + l * 2 * DD,
                                     t, n, 2 * DD, DD, 1);
        }
        // GEMM2: hn = bn(t @ W2 + b2) (+relu if l<L-1)  [n,128]
        {
            float* outp = (l == L - 1) ? (float*)d_out : hnxt;
            dim3 g((n + BM - 1) / BM, 1);
            gemm_fused_k<<<g, 256>>>(t, nullptr, nullptr,
                                     W2 + (size_t)l * 2 * DD * DD, b2 + l * DD,
                                     bng + l * DD, bnb + l * DD,
                                     bnm + l * DD, bnv + l * DD,
                                     outp, n, DD, 2 * DD, (l < L - 1) ? 1 : 0);
        }
        if (l < L - 1) {
            // vt = gsum + vn; vtt = relu(bn1(vt @ vnW1 + vnb1))
            dim3 g1((GG + BM - 1) / BM, 2);
            gemm_fused_k<<<g1, 256>>>(vn, gsum, nullptr,
                                      vnW1 + (size_t)l * DD * 2 * DD, vnb1 + l * 2 * DD,
                                      vbn1g + l * 2 * DD, vbn1b + l * 2 * DD,
                                      vbn1m + l * 2 * DD, vbn1v + l * 2 * DD,
                                      vt, GG, 2 * DD, DD, 1);
            // vn = relu(bn2(vtt @ vnW2 + vnb2))
            dim3 g2((GG + BM - 1) / BM, 1);
            gemm_fused_k<<<g2, 256>>>(vt, nullptr, nullptr,
                                      vnW2 + (size_t)l * 2 * DD * DD, vnb2 + l * DD,
                                      vbn2g + l * DD, vbn2b + l * DD,
                                      vbn2m + l * DD, vbn2v + l * DD,
                                      vn, GG, DD, 2 * DD, 1);
        }
        float* tmp = hcur; hcur = hnxt; hnxt = tmp;
    }
}

// round 4
// speedup vs baseline: 1.3827x; 1.3827x over previous
#include <cuda_runtime.h>
#include <cuda_bf16.h>
#include <cstdint>

#define MAXN 50000
#define MAXE 800000
#define GG   1024
#define DD   128
#define LL   3

// ---------------------------------------------------------------------------
// Scratch (static __device__ — no allocations allowed). Total ~110 MB.
// ---------------------------------------------------------------------------
__device__ float g_h[MAXN * DD];
__device__ float g_agg[MAXN * DD];
__device__ float g_t[MAXN * 2 * DD];
__device__ float g_vn[GG * DD];
__device__ float g_gsum[GG * DD];
__device__ float g_vt[GG * 2 * DD];
__device__ float g_cb[LL * 1000 * DD];      // combined bond tables
__device__ int   g_combo[MAXE];
// Preconverted weights: B^T images [N][K] bf16 hi/lo. 10 slots of 32768:
// W1 l0..2, W2 l0..2, vn1 l0..1, vn2 l0..1
__device__ __nv_bfloat16 g_Bhi[10 * 32768];
__device__ __nv_bfloat16 g_Blo[10 * 32768];

// ---------------------------------------------------------------------------
// PTX helpers
// ---------------------------------------------------------------------------
__device__ __forceinline__ uint32_t cvta_s(const void* p) {
    uint32_t a;
    asm("{ .reg .u64 t; cvta.to.shared.u64 t, %1; cvt.u32.u64 %0, t; }"
        : "=r"(a) : "l"(p));
    return a;
}
#define LDSM_X4(r0, r1, r2, r3, addr)                                          \
    asm volatile("ldmatrix.sync.aligned.m8n8.x4.shared.b16 {%0,%1,%2,%3}, [%4];"\
                 : "=r"(r0), "=r"(r1), "=r"(r2), "=r"(r3) : "r"(addr))
#define MMA_BF16(d0, d1, d2, d3, a0, a1, a2, a3, b0, b1)                       \
    asm volatile("mma.sync.aligned.m16n8k16.row.col.f32.bf16.bf16.f32 "        \
                 "{%0,%1,%2,%3}, {%4,%5,%6,%7}, {%8,%9}, {%0,%1,%2,%3};"       \
                 : "+f"(d0), "+f"(d1), "+f"(d2), "+f"(d3)                      \
                 : "r"(a0), "r"(a1), "r"(a2), "r"(a3), "r"(b0), "r"(b1))

// ---------------------------------------------------------------------------
// AtomEncoder
// ---------------------------------------------------------------------------
__global__ void atom_encode_k(const int* __restrict__ xa,
                              const float* __restrict__ emb,
                              float* __restrict__ h, int n) {
    int idx = blockIdx.x * blockDim.x + threadIdx.x;
    if (idx >= n * 32) return;
    int node = idx >> 5;
    int c4 = (idx & 31) << 2;
    float4 s = make_float4(0.f, 0.f, 0.f, 0.f);
#pragma unroll
    for (int f = 0; f < 9; f++) {
        int v = xa[node * 9 + f];
        float4 e = *(const float4*)(emb + (f * 100 + v) * DD + c4);
        s.x += e.x; s.y += e.y; s.z += e.z; s.w += e.w;
    }
    *(float4*)(h + node * DD + c4) = s;
}

__global__ void vn_init_k(const float* __restrict__ v0, float* __restrict__ vn) {
    int idx = blockIdx.x * blockDim.x + threadIdx.x;
    if (idx >= GG * 32) return;
    int c4 = (idx & 31) << 2;
    *(float4*)(vn + idx * 4) = *(const float4*)(v0 + c4);
}

__global__ void gsum_zero_k(float* __restrict__ gsum) {
    int idx = blockIdx.x * blockDim.x + threadIdx.x;
    if (idx < GG * 32)
        *(float4*)(gsum + idx * 4) = make_float4(0.f, 0.f, 0.f, 0.f);
}

// h += vn[batch]; agg = 0; optionally gsum[batch] += h (post-update h)
__global__ void add_vn_zero_k(float* __restrict__ h, const float* __restrict__ vn,
                              const int* __restrict__ batch, float* __restrict__ agg,
                              float* __restrict__ gsum, int n, int dosum) {
    int idx = blockIdx.x * blockDim.x + threadIdx.x;
    if (idx >= n * 32) return;
    int node = idx >> 5;
    int c4 = (idx & 31) << 2;
    int g = batch[node];
    float4 hv = *(float4*)(h + idx * 4);
    float4 vv = *(const float4*)(vn + g * DD + c4);
    hv.x += vv.x; hv.y += vv.y; hv.z += vv.z; hv.w += vv.w;
    *(float4*)(h + idx * 4) = hv;
    *(float4*)(agg + idx * 4) = make_float4(0.f, 0.f, 0.f, 0.f);
    if (dosum) {
        float* p = gsum + g * DD + c4;
        asm volatile("red.global.add.v4.f32 [%0], {%1,%2,%3,%4};"
                     :: "l"(p), "f"(hv.x), "f"(hv.y), "f"(hv.z), "f"(hv.w)
                     : "memory");
    }
}

// ---------------------------------------------------------------------------
// Bond combo precompute
// ---------------------------------------------------------------------------
__global__ void combo_idx_k(const int* __restrict__ ea, int* __restrict__ combo,
                            int ecnt) {
    int j = blockIdx.x * blockDim.x + threadIdx.x;
    if (j >= ecnt) return;
    combo[j] = ea[j * 3] * 100 + ea[j * 3 + 1] * 10 + ea[j * 3 + 2];
}

__global__ void combo_tbl_k(const float* __restrict__ bond,
                            float* __restrict__ cb) {
    int idx = blockIdx.x * blockDim.x + threadIdx.x;
    if (idx >= LL * 1000 * 32) return;
    int c4 = (idx & 31) << 2;
    int i = (idx >> 5) % 1000;
    int l = (idx >> 5) / 1000;
    int f0 = i / 100, f1 = (i / 10) % 10, f2 = i % 10;
    float4 v0 = *(const float4*)(bond + ((size_t)(l * 3 + 0) * 10 + f0) * DD + c4);
    float4 v1 = *(const float4*)(bond + ((size_t)(l * 3 + 1) * 10 + f1) * DD + c4);
    float4 v2 = *(const float4*)(bond + ((size_t)(l * 3 + 2) * 10 + f2) * DD + c4);
    float4 o;
    o.x = v0.x + v1.x + v2.x; o.y = v0.y + v1.y + v2.y;
    o.z = v0.z + v1.z + v2.z; o.w = v0.w + v1.w + v2.w;
    *(float4*)(cb + ((size_t)(l * 1000 + i)) * DD + c4) = o;
}

// ---------------------------------------------------------------------------
// Edge kernel: agg[dst] += relu(h[src] + cb[combo])
// ---------------------------------------------------------------------------
__global__ void edge_k2(const int* __restrict__ ei, const int* __restrict__ combo,
                        const float* __restrict__ cb, const float* __restrict__ h,
                        float* __restrict__ agg, int ecnt) {
    int lane = threadIdx.x & 31;
    int warp = (blockIdx.x * blockDim.x + threadIdx.x) >> 5;
    int nwarps = (gridDim.x * blockDim.x) >> 5;
    int c = lane << 2;
    for (int j = warp; j < ecnt; j += nwarps) {
        int src = ei[j];
        int dst = ei[ecnt + j];
        int cm = combo[j];
        float4 hv = *(const float4*)(h + (size_t)src * DD + c);
        float4 ev = *(const float4*)(cb + (size_t)cm * DD + c);
        float x = fmaxf(hv.x + ev.x, 0.f);
        float y = fmaxf(hv.y + ev.y, 0.f);
        float z = fmaxf(hv.z + ev.z, 0.f);
        float w = fmaxf(hv.w + ev.w, 0.f);
        float* p = agg + (size_t)dst * DD + c;
        asm volatile("red.global.add.v4.f32 [%0], {%1,%2,%3,%4};"
                     :: "l"(p), "f"(x), "f"(y), "f"(z), "f"(w) : "memory");
    }
}

// ---------------------------------------------------------------------------
// Weight preprocessing: W [Kdim, Ndim] row-major -> B^T [N][K] bf16 hi/lo
// ---------------------------------------------------------------------------
__global__ void preproc_k(const float* __restrict__ W, int Kdim, int Ndim,
                          __nv_bfloat16* __restrict__ ohi,
                          __nv_bfloat16* __restrict__ olo) {
    int idx = blockIdx.x * blockDim.x + threadIdx.x;
    if (idx >= Kdim * Ndim) return;
    int k = idx / Ndim, n = idx % Ndim;
    float w = W[idx];
    __nv_bfloat16 hi = __float2bfloat16_rn(w);
    __nv_bfloat16 lo = __float2bfloat16_rn(w - __bfloat162float(hi));
    ohi[(size_t)n * Kdim + k] = hi;
    olo[(size_t)n * Kdim + k] = lo;
}

// ---------------------------------------------------------------------------
// mma.sync bf16 GEMM (3-term hi/lo split ≈ fp32):
//   C = act( bn( (al*A + A2) @ W + lin_b ) )
// CTA tile 128(M) x 64(N), BK=64, 8 warps as 4(m) x 2(n); warp tile 32x32.
// Per-thread: 32 accum + 32 fragment regs -> ~100 regs, no spill.
// Smem: padded stride 72 halves (144 B) -> conflict-free ldmatrix. 54 KB.
// ---------------------------------------------------------------------------
#define ASTR 72
#define SA_HI 0
#define SA_LO 18432
#define SB_HI 36864
#define SB_LO 46080
#define SM_TOT 55296

__global__ void __launch_bounds__(256)
gemm_mma_k(const float* __restrict__ A, const float* __restrict__ A2,
           const float* __restrict__ alpha_ptr,
           const __nv_bfloat16* __restrict__ Bhi_g,
           const __nv_bfloat16* __restrict__ Blo_g,
           const float* __restrict__ lin_b,
           const float* __restrict__ bng, const float* __restrict__ bnb,
           const float* __restrict__ bnm, const float* __restrict__ bnv,
           float* __restrict__ C, int M, int N, int K, int do_relu) {
    extern __shared__ char dsm[];
    __shared__ float s_sc[64], s_sb[64];

    int tid = threadIdx.x;
    int lane = tid & 31, wid = tid >> 5;
    int bm = blockIdx.x * 128;
    int bn = blockIdx.y * 64;

    if (tid < 64) {
        int col = bn + tid;
        float s = bng[col] * rsqrtf(bnv[col] + 1e-5f);
        s_sc[tid] = s;
        s_sb[tid] = (lin_b[col] - bnm[col]) * s + bnb[col];
    }

    float al = alpha_ptr ? (1.0f + *alpha_ptr) : 1.0f;
    uint32_t smbase = cvta_s(dsm);

    int wm = (wid >> 1) * 32;      // warp m-offset (0,32,64,96)
    int wn = (wid & 1) * 32;       // warp n-offset (0,32)

    float acc[2][4][4];
#pragma unroll
    for (int a = 0; a < 2; a++)
#pragma unroll
        for (int b = 0; b < 4; b++)
#pragma unroll
            for (int q = 0; q < 4; q++) acc[a][b][q] = 0.f;

    int r8 = lane & 7, g = lane >> 3;
    int arow = wm + ((g & 1) << 3) + r8;
    int acolg = (g >> 1) << 3;
    int brow = wn + ((g >> 1) << 3) + r8;
    int bcolg = (g & 1) << 3;

    int nch = K >> 6;
    for (int ch = 0; ch < nch; ch++) {
        int cc = ch << 6;
        // ---- A: fp32 load (+fused z = al*A + A2), bf16 hi/lo split -> smem
        for (int i = tid; i < 2048; i += 256) {
            int row = i >> 4, c4 = (i & 15) << 2;
            float4 v = make_float4(0.f, 0.f, 0.f, 0.f);
            if (bm + row < M) {
                v = *(const float4*)(A + (size_t)(bm + row) * K + cc + c4);
                if (A2) {
                    float4 w = *(const float4*)(A2 + (size_t)(bm + row) * K + cc + c4);
                    v.x = al * v.x + w.x; v.y = al * v.y + w.y;
                    v.z = al * v.z + w.z; v.w = al * v.w + w.w;
                }
            }
            __nv_bfloat16 h0 = __float2bfloat16_rn(v.x);
            __nv_bfloat16 h1 = __float2bfloat16_rn(v.y);
            __nv_bfloat16 h2 = __float2bfloat16_rn(v.z);
            __nv_bfloat16 h3 = __float2bfloat16_rn(v.w);
            __nv_bfloat16 l0 = __float2bfloat16_rn(v.x - __bfloat162float(h0));
            __nv_bfloat16 l1 = __float2bfloat16_rn(v.y - __bfloat162float(h1));
            __nv_bfloat16 l2 = __float2bfloat16_rn(v.z - __bfloat162float(h2));
            __nv_bfloat16 l3 = __float2bfloat16_rn(v.w - __bfloat162float(h3));
            uint32_t hp0 = (uint32_t)__bfloat16_as_ushort(h0) |
                           ((uint32_t)__bfloat16_as_ushort(h1) << 16);
            uint32_t hp1 = (uint32_t)__bfloat16_as_ushort(h2) |
                           ((uint32_t)__bfloat16_as_ushort(h3) << 16);
            uint32_t lp0 = (uint32_t)__bfloat16_as_ushort(l0) |
                           ((uint32_t)__bfloat16_as_ushort(l1) << 16);
            uint32_t lp1 = (uint32_t)__bfloat16_as_ushort(l2) |
                           ((uint32_t)__bfloat16_as_ushort(l3) << 16);
            int off = (row * ASTR + c4) * 2;
            *(uint2*)(dsm + SA_HI + off) = make_uint2(hp0, hp1);
            *(uint2*)(dsm + SA_LO + off) = make_uint2(lp0, lp1);
        }
        // ---- B: copy preconverted bf16 [N][K] chunk -> smem
        for (int i = tid; i < 512; i += 256) {
            int row = i >> 3, c8 = (i & 7) << 3;
            uint4 vh = *(const uint4*)(Bhi_g + (size_t)(bn + row) * K + cc + c8);
            uint4 vl = *(const uint4*)(Blo_g + (size_t)(bn + row) * K + cc + c8);
            int off = (row * ASTR + c8) * 2;
            *(uint4*)(dsm + SB_HI + off) = vh;
            *(uint4*)(dsm + SB_LO + off) = vl;
        }
        __syncthreads();

        // ---- compute: 4 k16 steps
#pragma unroll
        for (int ks = 0; ks < 4; ks++) {
            int kk = ks << 4;
            uint32_t ah0, ah1, ah2, ah3, ah4, ah5, ah6, ah7;
            uint32_t am0, am1, am2, am3, am4, am5, am6, am7;
            uint32_t bh0, bh1, bh2, bh3, bh4, bh5, bh6, bh7;
            uint32_t bm0, bm1, bm2, bm3, bm4, bm5, bm6, bm7;
            {
                uint32_t ad0 = smbase + SA_HI + ((arow) * ASTR + kk + acolg) * 2;
                uint32_t ad1 = smbase + SA_HI + ((arow + 16) * ASTR + kk + acolg) * 2;
                LDSM_X4(ah0, ah1, ah2, ah3, ad0);
                LDSM_X4(ah4, ah5, ah6, ah7, ad1);
                LDSM_X4(am0, am1, am2, am3, ad0 + (SA_LO - SA_HI));
                LDSM_X4(am4, am5, am6, am7, ad1 + (SA_LO - SA_HI));
                uint32_t bd0 = smbase + SB_HI + ((brow) * ASTR + kk + bcolg) * 2;
                uint32_t bd1 = smbase + SB_HI + ((brow + 16) * ASTR + kk + bcolg) * 2;
                LDSM_X4(bh0, bh1, bh2, bh3, bd0);
                LDSM_X4(bh4, bh5, bh6, bh7, bd1);
                LDSM_X4(bm0, bm1, bm2, bm3, bd0 + (SB_LO - SB_HI));
                LDSM_X4(bm4, bm5, bm6, bm7, bd1 + (SB_LO - SB_HI));
            }
#define DO_NT(mt, nt, B0, B1, BL0, BL1, A0, A1, A2_, A3, AL0, AL1, AL2, AL3)    \
            MMA_BF16(acc[mt][nt][0], acc[mt][nt][1], acc[mt][nt][2],            \
                     acc[mt][nt][3], A0, A1, A2_, A3, B0, B1);                  \
            MMA_BF16(acc[mt][nt][0], acc[mt][nt][1], acc[mt][nt][2],            \
                     acc[mt][nt][3], A0, A1, A2_, A3, BL0, BL1);                \
            MMA_BF16(acc[mt][nt][0], acc[mt][nt][1], acc[mt][nt][2],            \
                     acc[mt][nt][3], AL0, AL1, AL2, AL3, B0, B1);
            DO_NT(0, 0, bh0, bh1, bm0, bm1, ah0, ah1, ah2, ah3, am0, am1, am2, am3)
            DO_NT(0, 1, bh2, bh3, bm2, bm3, ah0, ah1, ah2, ah3, am0, am1, am2, am3)
            DO_NT(0, 2, bh4, bh5, bm4, bm5, ah0, ah1, ah2, ah3, am0, am1, am2, am3)
            DO_NT(0, 3, bh6, bh7, bm6, bm7, ah0, ah1, ah2, ah3, am0, am1, am2, am3)
            DO_NT(1, 0, bh0, bh1, bm0, bm1, ah4, ah5, ah6, ah7, am4, am5, am6, am7)
            DO_NT(1, 1, bh2, bh3, bm2, bm3, ah4, ah5, ah6, ah7, am4, am5, am6, am7)
            DO_NT(1, 2, bh4, bh5, bm4, bm5, ah4, ah5, ah6, ah7, am4, am5, am6, am7)
            DO_NT(1, 3, bh6, bh7, bm6, bm7, ah4, ah5, ah6, ah7, am4, am5, am6, am7)
#undef DO_NT
        }
        __syncthreads();
    }

    // ---- epilogue: BN fold + optional relu
    int rq = lane >> 2, cq = (lane & 3) * 2;
#pragma unroll
    for (int mt = 0; mt < 2; mt++) {
        int r0 = bm + wm + mt * 16 + rq;
#pragma unroll
        for (int nt = 0; nt < 4; nt++) {
            int c0 = wn + nt * 8 + cq;
            float s0 = s_sc[c0], s1 = s_sc[c0 + 1];
            float t0 = s_sb[c0], t1 = s_sb[c0 + 1];
            float v0 = acc[mt][nt][0] * s0 + t0;
            float v1 = acc[mt][nt][1] * s1 + t1;
            float v2 = acc[mt][nt][2] * s0 + t0;
            float v3 = acc[mt][nt][3] * s1 + t1;
            if (do_relu) {
                v0 = fmaxf(v0, 0.f); v1 = fmaxf(v1, 0.f);
                v2 = fmaxf(v2, 0.f); v3 = fmaxf(v3, 0.f);
            }
            if (r0 < M)
                *(float2*)(C + (size_t)r0 * N + bn + c0) = make_float2(v0, v1);
            if (r0 + 8 < M)
                *(float2*)(C + (size_t)(r0 + 8) * N + bn + c0) = make_float2(v2, v3);
        }
    }
}

// ---------------------------------------------------------------------------
// Host driver
// ---------------------------------------------------------------------------
extern "C" void kernel_launch(void* const* d_in, const int* in_sizes, int n_in,
                              void* d_out, int out_size) {
    const int*   x_atom  = (const int*)d_in[0];
    const int*   ei      = (const int*)d_in[1];
    const int*   ea      = (const int*)d_in[2];
    const int*   batch   = (const int*)d_in[3];
    const float* atomemb = (const float*)d_in[4];
    const float* vn0     = (const float*)d_in[5];
    const float* bond    = (const float*)d_in[6];
    const float* eps     = (const float*)d_in[7];
    const float* W1      = (const float*)d_in[8];
    const float* b1      = (const float*)d_in[9];
    const float* bn1g    = (const float*)d_in[10];
    const float* bn1b    = (const float*)d_in[11];
    const float* bn1m    = (const float*)d_in[12];
    const float* bn1v    = (const float*)d_in[13];
    const float* W2      = (const float*)d_in[14];
    const float* b2      = (const float*)d_in[15];
    const float* bng     = (const float*)d_in[16];
    const float* bnb     = (const float*)d_in[17];
    const float* bnm     = (const float*)d_in[18];
    const float* bnv     = (const float*)d_in[19];
    const float* vnW1    = (const float*)d_in[20];
    const float* vnb1    = (const float*)d_in[21];
    const float* vbn1g   = (const float*)d_in[22];
    const float* vbn1b   = (const float*)d_in[23];
    const float* vbn1m   = (const float*)d_in[24];
    const float* vbn1v   = (const float*)d_in[25];
    const float* vnW2    = (const float*)d_in[26];
    const float* vnb2    = (const float*)d_in[27];
    const float* vbn2g   = (const float*)d_in[28];
    const float* vbn2b   = (const float*)d_in[29];
    const float* vbn2m   = (const float*)d_in[30];
    const float* vbn2v   = (const float*)d_in[31];

    int n = in_sizes[3];
    int ecnt = in_sizes[1] / 2;

    float *h, *agg, *t, *vn, *gsum, *vt, *cb;
    int* combo;
    __nv_bfloat16 *Bhi, *Blo;
    cudaGetSymbolAddress((void**)&h, g_h);
    cudaGetSymbolAddress((void**)&agg, g_agg);
    cudaGetSymbolAddress((void**)&t, g_t);
    cudaGetSymbolAddress((void**)&vn, g_vn);
    cudaGetSymbolAddress((void**)&gsum, g_gsum);
    cudaGetSymbolAddress((void**)&vt, g_vt);
    cudaGetSymbolAddress((void**)&cb, g_cb);
    cudaGetSymbolAddress((void**)&combo, g_combo);
    cudaGetSymbolAddress((void**)&Bhi, g_Bhi);
    cudaGetSymbolAddress((void**)&Blo, g_Blo);

    cudaFuncSetAttribute(gemm_mma_k, cudaFuncAttributeMaxDynamicSharedMemorySize,
                         SM_TOT);

    const int WSLOT = 32768;
    int nThreads = 256;
    int gridND = (n * 32 + nThreads - 1) / nThreads;
    int gridW = (32768 + 255) / 256;

    for (int l = 0; l < LL; l++) {
        preproc_k<<<gridW, 256>>>(W1 + (size_t)l * 128 * 256, 128, 256,
                                  Bhi + (size_t)l * WSLOT, Blo + (size_t)l * WSLOT);
        preproc_k<<<gridW, 256>>>(W2 + (size_t)l * 256 * 128, 256, 128,
                                  Bhi + (size_t)(3 + l) * WSLOT,
                                  Blo + (size_t)(3 + l) * WSLOT);
    }
    for (int l = 0; l < LL - 1; l++) {
        preproc_k<<<gridW, 256>>>(vnW1 + (size_t)l * 128 * 256, 128, 256,
                                  Bhi + (size_t)(6 + l) * WSLOT,
                                  Blo + (size_t)(6 + l) * WSLOT);
        preproc_k<<<gridW, 256>>>(vnW2 + (size_t)l * 256 * 128, 256, 128,
                                  Bhi + (size_t)(8 + l) * WSLOT,
                                  Blo + (size_t)(8 + l) * WSLOT);
    }
    combo_idx_k<<<(ecnt + 255) / 256, 256>>>(ea, combo, ecnt);
    combo_tbl_k<<<(LL * 1000 * 32 + 255) / 256, 256>>>(bond, cb);

    atom_encode_k<<<gridND, nThreads>>>(x_atom, atomemb, h, n);
    vn_init_k<<<(GG * 32 + nThreads - 1) / nThreads, nThreads>>>(vn0, vn);

    int gridM = (n + 127) / 128;
    for (int l = 0; l < LL; l++) {
        int dosum = (l < LL - 1) ? 1 : 0;
        if (dosum)
            gsum_zero_k<<<(GG * 32 + 255) / 256, 256>>>(gsum);
        add_vn_zero_k<<<gridND, nThreads>>>(h, vn, batch, agg, gsum, n, dosum);
        edge_k2<<<1480, nThreads>>>(ei, combo, cb + (size_t)l * 1000 * DD,
                                    h, agg, ecnt);

        // GEMM1: t = relu(bn1(((1+eps)h + agg) @ W1 + b1))   [n,256]
        {
            dim3 g(gridM, 4);
            gemm_mma_k<<<g, 256, SM_TOT>>>(
                h, agg, eps + l,
                Bhi + (size_t)l * WSLOT, Blo + (size_t)l * WSLOT,
                b1 + l * 2 * DD, bn1g + l * 2 * DD, bn1b + l * 2 * DD,
                bn1m + l * 2 * DD, bn1v + l * 2 * DD,
                t, n, 256, 128, 1);
        }
        // GEMM2: hn = bn(t @ W2 + b2) (+relu if l<L-1)  -> overwrite h
        {
            float* outp = (l == LL - 1) ? (float*)d_out : h;
            dim3 g(gridM, 2);
            gemm_mma_k<<<g, 256, SM_TOT>>>(
                t, nullptr, nullptr,
                Bhi + (size_t)(3 + l) * WSLOT, Blo + (size_t)(3 + l) * WSLOT,
                b2 + l * DD, bng + l * DD, bnb + l * DD, bnm + l * DD,
                bnv + l * DD,
                outp, n, 128, 256, (l < LL - 1) ? 1 : 0);
        }
        if (l < LL - 1) {
            // vt = relu(bn1((gsum + vn) @ vnW1 + vnb1))  [G,256]
            dim3 g1(GG / 128, 4);
            gemm_mma_k<<<g1, 256, SM_TOT>>>(
                vn, gsum, nullptr,
                Bhi + (size_t)(6 + l) * WSLOT, Blo + (size_t)(6 + l) * WSLOT,
                vnb1 + l * 2 * DD, vbn1g + l * 2 * DD, vbn1b + l * 2 * DD,
                vbn1m + l * 2 * DD, vbn1v + l * 2 * DD,
                vt, GG, 256, 128, 1);
            // vn = relu(bn2(vt @ vnW2 + vnb2))  [G,128]
            dim3 g2(GG / 128, 2);
            gemm_mma_k<<<g2, 256, SM_TOT>>>(
                vt, nullptr, nullptr,
                Bhi + (size_t)(8 + l) * WSLOT, Blo + (size_t)(8 + l) * WSLOT,
                vnb2 + l * DD, vbn2g + l * DD, vbn2b + l * DD,
                vbn2m + l * DD, vbn2v + l * DD,
                vn, GG, 128, 256, 1);
        }
    }
}

// round 5
// speedup vs baseline: 1.7008x; 1.2301x over previous
#include <cuda_runtime.h>
#include <cuda_bf16.h>
#include <cstdint>

#define MAXN 50000
#define MAXE 800000
#define GG   1024
#define DD   128
#define LL   3

// ---------------------------------------------------------------------------
// Static scratch (loaded at module init; counted before harness checkpoint)
// ---------------------------------------------------------------------------
__device__ float g_h[MAXN * DD];                 // node features f32
__device__ __nv_bfloat16 g_zhi[MAXN * DD];       // GIN input, bf16 hi
__device__ __nv_bfloat16 g_zlo[MAXN * DD];       // GIN input, bf16 lo
__device__ __nv_bfloat16 g_thi[MAXN * 2 * DD];   // MLP hidden, bf16 hi
__device__ __nv_bfloat16 g_tlo[MAXN * 2 * DD];   // MLP hidden, bf16 lo
__device__ float g_vn[GG * DD];
__device__ float g_gsum[GG * DD];
__device__ float g_vt[GG * 2 * DD];
__device__ float g_cb[LL * 1000 * DD];           // combined bond tables
__device__ int   g_cnt[MAXN];
__device__ int   g_off[MAXN + 1];
__device__ int   g_cur[MAXN];
__device__ int   g_csrs[MAXE];                   // CSR src
__device__ int   g_csrc[MAXE];                   // CSR combo idx
// Preconverted weights: B^T images [N][K] bf16 hi/lo. 10 slots of 32768:
// W1 l0..2, W2 l0..2, vn1 l0..1, vn2 l0..1
__device__ __nv_bfloat16 g_Bhi[10 * 32768];
__device__ __nv_bfloat16 g_Blo[10 * 32768];

// ---------------------------------------------------------------------------
// PTX helpers
// ---------------------------------------------------------------------------
__device__ __forceinline__ uint32_t cvta_s(const void* p) {
    uint32_t a;
    asm("{ .reg .u64 t; cvta.to.shared.u64 t, %1; cvt.u32.u64 %0, t; }"
        : "=r"(a) : "l"(p));
    return a;
}
#define LDSM_X4(r0, r1, r2, r3, addr)                                          \
    asm volatile("ldmatrix.sync.aligned.m8n8.x4.shared.b16 {%0,%1,%2,%3}, [%4];"\
                 : "=r"(r0), "=r"(r1), "=r"(r2), "=r"(r3) : "r"(addr))
#define MMA_BF16(d0, d1, d2, d3, a0, a1, a2, a3, b0, b1)                       \
    asm volatile("mma.sync.aligned.m16n8k16.row.col.f32.bf16.bf16.f32 "        \
                 "{%0,%1,%2,%3}, {%4,%5,%6,%7}, {%8,%9}, {%0,%1,%2,%3};"       \
                 : "+f"(d0), "+f"(d1), "+f"(d2), "+f"(d3)                      \
                 : "r"(a0), "r"(a1), "r"(a2), "r"(a3), "r"(b0), "r"(b1))

__device__ __forceinline__ void split_bf16(float v, unsigned short& hi,
                                           unsigned short& lo) {
    __nv_bfloat16 h = __float2bfloat16_rn(v);
    hi = __bfloat16_as_ushort(h);
    lo = __bfloat16_as_ushort(__float2bfloat16_rn(v - __bfloat162float(h)));
}

// ---------------------------------------------------------------------------
// AtomEncoder / init
// ---------------------------------------------------------------------------
__global__ void atom_encode_k(const int* __restrict__ xa,
                              const float* __restrict__ emb,
                              float* __restrict__ h, int n) {
    int idx = blockIdx.x * blockDim.x + threadIdx.x;
    if (idx >= n * 32) return;
    int node = idx >> 5;
    int c4 = (idx & 31) << 2;
    float4 s = make_float4(0.f, 0.f, 0.f, 0.f);
#pragma unroll
    for (int f = 0; f < 9; f++) {
        int v = xa[node * 9 + f];
        float4 e = *(const float4*)(emb + (f * 100 + v) * DD + c4);
        s.x += e.x; s.y += e.y; s.z += e.z; s.w += e.w;
    }
    *(float4*)(h + node * DD + c4) = s;
}

__global__ void vn_init_k(const float* __restrict__ v0, float* __restrict__ vn) {
    int idx = blockIdx.x * blockDim.x + threadIdx.x;
    if (idx >= GG * 32) return;
    int c4 = (idx & 31) << 2;
    *(float4*)(vn + idx * 4) = *(const float4*)(v0 + c4);
}

__global__ void gsum_zero_k(float* __restrict__ gsum) {
    int idx = blockIdx.x * blockDim.x + threadIdx.x;
    if (idx < GG * 32)
        *(float4*)(gsum + idx * 4) = make_float4(0.f, 0.f, 0.f, 0.f);
}

// h += vn[batch]; optionally gsum[batch] += h (post-update)
__global__ void add_vn_k(float* __restrict__ h, const float* __restrict__ vn,
                         const int* __restrict__ batch,
                         float* __restrict__ gsum, int n, int dosum) {
    int idx = blockIdx.x * blockDim.x + threadIdx.x;
    if (idx >= n * 32) return;
    int node = idx >> 5;
    int c4 = (idx & 31) << 2;
    int g = batch[node];
    float4 hv = *(float4*)(h + idx * 4);
    float4 vv = *(const float4*)(vn + g * DD + c4);
    hv.x += vv.x; hv.y += vv.y; hv.z += vv.z; hv.w += vv.w;
    *(float4*)(h + idx * 4) = hv;
    if (dosum) {
        float* p = gsum + g * DD + c4;
        asm volatile("red.global.add.v4.f32 [%0], {%1,%2,%3,%4};"
                     :: "l"(p), "f"(hv.x), "f"(hv.y), "f"(hv.z), "f"(hv.w)
                     : "memory");
    }
}

// ---------------------------------------------------------------------------
// CSR build (once per launch; edge structure is layer-invariant)
// ---------------------------------------------------------------------------
__global__ void cnt_zero_k(int* __restrict__ cnt, int n) {
    int i = blockIdx.x * blockDim.x + threadIdx.x;
    if (i < n) cnt[i] = 0;
}
__global__ void count_k(const int* __restrict__ ei, int* __restrict__ cnt,
                        int ecnt) {
    int j = blockIdx.x * blockDim.x + threadIdx.x;
    if (j < ecnt) atomicAdd(&cnt[ei[ecnt + j]], 1);
}
__global__ void scan_k(const int* __restrict__ cnt, int* __restrict__ off,
                       int* __restrict__ cur, int n, int ecnt) {
    __shared__ int part[1024];
    int t = threadIdx.x;
    int chunk = (n + 1023) >> 10;
    int beg = t * chunk;
    int end = min(beg + chunk, n);
    int s = 0;
    for (int i = beg; i < end; i++) s += cnt[i];
    part[t] = s;
    __syncthreads();
    for (int d = 1; d < 1024; d <<= 1) {
        int v = (t >= d) ? part[t - d] : 0;
        __syncthreads();
        if (t >= d) part[t] += v;
        __syncthreads();
    }
    int run = (t == 0) ? 0 : part[t - 1];
    for (int i = beg; i < end; i++) {
        off[i] = run;
        cur[i] = run;
        run += cnt[i];
    }
    if (t == 0) off[n] = ecnt;
}
__global__ void scatter_k(const int* __restrict__ ei, const int* __restrict__ ea,
                          int* __restrict__ cur, int* __restrict__ csrs,
                          int* __restrict__ csrc, int ecnt) {
    int j = blockIdx.x * blockDim.x + threadIdx.x;
    if (j >= ecnt) return;
    int dst = ei[ecnt + j];
    int pos = atomicAdd(&cur[dst], 1);
    csrs[pos] = ei[j];
    csrc[pos] = ea[j * 3] * 100 + ea[j * 3 + 1] * 10 + ea[j * 3 + 2];
}

// ---------------------------------------------------------------------------
// Bond combo table
// ---------------------------------------------------------------------------
__global__ void combo_tbl_k(const float* __restrict__ bond,
                            float* __restrict__ cb) {
    int idx = blockIdx.x * blockDim.x + threadIdx.x;
    if (idx >= LL * 1000 * 32) return;
    int c4 = (idx & 31) << 2;
    int i = (idx >> 5) % 1000;
    int l = (idx >> 5) / 1000;
    int f0 = i / 100, f1 = (i / 10) % 10, f2 = i % 10;
    float4 v0 = *(const float4*)(bond + ((size_t)(l * 3 + 0) * 10 + f0) * DD + c4);
    float4 v1 = *(const float4*)(bond + ((size_t)(l * 3 + 1) * 10 + f1) * DD + c4);
    float4 v2 = *(const float4*)(bond + ((size_t)(l * 3 + 2) * 10 + f2) * DD + c4);
    float4 o;
    o.x = v0.x + v1.x + v2.x; o.y = v0.y + v1.y + v2.y;
    o.z = v0.z + v1.z + v2.z; o.w = v0.w + v1.w + v2.w;
    *(float4*)(cb + ((size_t)(l * 1000 + i)) * DD + c4) = o;
}

// ---------------------------------------------------------------------------
// Edge gather (CSR, atomic-free) + fused GIN combine + bf16 hi/lo split:
//   z[node] = (1+eps)*h[node] + sum_{e->node} relu(h[src_e] + cb[combo_e])
// One warp per node; lane owns 4 columns.
// ---------------------------------------------------------------------------
__global__ void edge_csr_k(const int* __restrict__ off,
                           const int* __restrict__ csrs,
                           const int* __restrict__ csrc,
                           const float* __restrict__ cb,
                           const float* __restrict__ h,
                           const float* __restrict__ eps_p,
                           __nv_bfloat16* __restrict__ zhi,
                           __nv_bfloat16* __restrict__ zlo, int n) {
    int warp = (blockIdx.x * blockDim.x + threadIdx.x) >> 5;
    if (warp >= n) return;
    int lane = threadIdx.x & 31;
    int c4 = lane << 2;
    float4 acc = make_float4(0.f, 0.f, 0.f, 0.f);
    int beg = off[warp], end = off[warp + 1];
    for (int base = beg; base < end; base += 32) {
        int m = min(32, end - base);
        int s = 0, cm = 0;
        if (base + lane < end) {
            s = csrs[base + lane];
            cm = csrc[base + lane];
        }
        for (int k = 0; k < m; k++) {
            int ss = __shfl_sync(0xffffffffu, s, k);
            int cc = __shfl_sync(0xffffffffu, cm, k);
            float4 hv = *(const float4*)(h + (size_t)ss * DD + c4);
            float4 ev = *(const float4*)(cb + (size_t)cc * DD + c4);
            acc.x += fmaxf(hv.x + ev.x, 0.f);
            acc.y += fmaxf(hv.y + ev.y, 0.f);
            acc.z += fmaxf(hv.z + ev.z, 0.f);
            acc.w += fmaxf(hv.w + ev.w, 0.f);
        }
    }
    float al = 1.0f + *eps_p;
    float4 hv = *(const float4*)(h + (size_t)warp * DD + c4);
    float z0 = al * hv.x + acc.x;
    float z1 = al * hv.y + acc.y;
    float z2 = al * hv.z + acc.z;
    float z3 = al * hv.w + acc.w;
    unsigned short h0, h1, h2, h3, l0, l1, l2, l3;
    split_bf16(z0, h0, l0); split_bf16(z1, h1, l1);
    split_bf16(z2, h2, l2); split_bf16(z3, h3, l3);
    uint2 hp = make_uint2((uint32_t)h0 | ((uint32_t)h1 << 16),
                          (uint32_t)h2 | ((uint32_t)h3 << 16));
    uint2 lp = make_uint2((uint32_t)l0 | ((uint32_t)l1 << 16),
                          (uint32_t)l2 | ((uint32_t)l3 << 16));
    *(uint2*)(zhi + (size_t)warp * DD + c4) = hp;
    *(uint2*)(zlo + (size_t)warp * DD + c4) = lp;
}

// ---------------------------------------------------------------------------
// Fused weight preprocessing, all 10 slots in ONE launch.
// ---------------------------------------------------------------------------
__global__ void preproc_all_k(const float* __restrict__ W1,
                              const float* __restrict__ W2,
                              const float* __restrict__ vnW1,
                              const float* __restrict__ vnW2,
                              __nv_bfloat16* __restrict__ Bhi,
                              __nv_bfloat16* __restrict__ Blo) {
    int idx = blockIdx.x * blockDim.x + threadIdx.x;
    if (idx >= 10 * 32768) return;
    int slot = idx >> 15;
    int r = idx & 32767;
    const float* W;
    int Nd;
    if (slot < 3)      { W = W1 + (size_t)slot * 32768;        Nd = 256; }
    else if (slot < 6) { W = W2 + (size_t)(slot - 3) * 32768;  Nd = 128; }
    else if (slot < 8) { W = vnW1 + (size_t)(slot - 6) * 32768; Nd = 256; }
    else               { W = vnW2 + (size_t)(slot - 8) * 32768; Nd = 128; }
    int Kd = 32768 / Nd;
    int k = r / Nd, nn = r % Nd;
    float w = W[r];
    unsigned short hi, lo;
    split_bf16(w, hi, lo);
    size_t o = (size_t)slot * 32768 + (size_t)nn * Kd + k;
    Bhi[o] = __ushort_as_bfloat16(hi);
    Blo[o] = __ushort_as_bfloat16(lo);
}

// ---------------------------------------------------------------------------
// mma.sync bf16 GEMM, A preconverted (hi/lo bf16 [M][K]):
//   C = act( bn( A @ W + lin_b ) )
// Output: either f32 C, or bf16 hi/lo split (for feeding the next GEMM).
// CTA tile 128x64, BK=64, 8 warps 4x2, warp tile 32x32.
// ---------------------------------------------------------------------------
#define ASTR 72
#define SA_HI 0
#define SA_LO 18432
#define SB_HI 36864
#define SB_LO 46080
#define SM_TOT 55296

__global__ void __launch_bounds__(256)
gemm_bf16_k(const __nv_bfloat16* __restrict__ Ahi,
            const __nv_bfloat16* __restrict__ Alo,
            const __nv_bfloat16* __restrict__ Bhi_g,
            const __nv_bfloat16* __restrict__ Blo_g,
            const float* __restrict__ lin_b,
            const float* __restrict__ bng, const float* __restrict__ bnb,
            const float* __restrict__ bnm, const float* __restrict__ bnv,
            float* __restrict__ Cf,
            __nv_bfloat16* __restrict__ Chi, __nv_bfloat16* __restrict__ Clo,
            int M, int N, int K, int do_relu) {
    extern __shared__ char dsm[];
    __shared__ float s_sc[64], s_sb[64];

    int tid = threadIdx.x;
    int lane = tid & 31, wid = tid >> 5;
    int bm = blockIdx.x * 128;
    int bn = blockIdx.y * 64;

    if (tid < 64) {
        int col = bn + tid;
        float s = bng[col] * rsqrtf(bnv[col] + 1e-5f);
        s_sc[tid] = s;
        s_sb[tid] = (lin_b[col] - bnm[col]) * s + bnb[col];
    }

    uint32_t smbase = cvta_s(dsm);
    int wm = (wid >> 1) * 32;
    int wn = (wid & 1) * 32;

    float acc[2][4][4];
#pragma unroll
    for (int a = 0; a < 2; a++)
#pragma unroll
        for (int b = 0; b < 4; b++)
#pragma unroll
            for (int q = 0; q < 4; q++) acc[a][b][q] = 0.f;

    int r8 = lane & 7, g = lane >> 3;
    int arow = wm + ((g & 1) << 3) + r8;
    int acolg = (g >> 1) << 3;
    int brow = wn + ((g >> 1) << 3) + r8;
    int bcolg = (g & 1) << 3;

    int nch = K >> 6;
    for (int ch = 0; ch < nch; ch++) {
        int cc = ch << 6;
        // ---- A: copy bf16 hi/lo chunk -> smem (8 bf16 per uint4)
        for (int i = tid; i < 1024; i += 256) {
            int row = i >> 3, c8 = (i & 7) << 3;
            uint4 vh = make_uint4(0u, 0u, 0u, 0u), vl = vh;
            if (bm + row < M) {
                vh = *(const uint4*)(Ahi + (size_t)(bm + row) * K + cc + c8);
                vl = *(const uint4*)(Alo + (size_t)(bm + row) * K + cc + c8);
            }
            int off = (row * ASTR + c8) * 2;
            *(uint4*)(dsm + SA_HI + off) = vh;
            *(uint4*)(dsm + SA_LO + off) = vl;
        }
        // ---- B: copy preconverted bf16 [N][K] chunk -> smem
        for (int i = tid; i < 512; i += 256) {
            int row = i >> 3, c8 = (i & 7) << 3;
            uint4 vh = *(const uint4*)(Bhi_g + (size_t)(bn + row) * K + cc + c8);
            uint4 vl = *(const uint4*)(Blo_g + (size_t)(bn + row) * K + cc + c8);
            int off = (row * ASTR + c8) * 2;
            *(uint4*)(dsm + SB_HI + off) = vh;
            *(uint4*)(dsm + SB_LO + off) = vl;
        }
        __syncthreads();

#pragma unroll
        for (int ks = 0; ks < 4; ks++) {
            int kk = ks << 4;
            uint32_t ah0, ah1, ah2, ah3, ah4, ah5, ah6, ah7;
            uint32_t am0, am1, am2, am3, am4, am5, am6, am7;
            uint32_t bh0, bh1, bh2, bh3, bh4, bh5, bh6, bh7;
            uint32_t bm0, bm1, bm2, bm3, bm4, bm5, bm6, bm7;
            {
                uint32_t ad0 = smbase + SA_HI + ((arow) * ASTR + kk + acolg) * 2;
                uint32_t ad1 = smbase + SA_HI + ((arow + 16) * ASTR + kk + acolg) * 2;
                LDSM_X4(ah0, ah1, ah2, ah3, ad0);
                LDSM_X4(ah4, ah5, ah6, ah7, ad1);
                LDSM_X4(am0, am1, am2, am3, ad0 + (SA_LO - SA_HI));
                LDSM_X4(am4, am5, am6, am7, ad1 + (SA_LO - SA_HI));
                uint32_t bd0 = smbase + SB_HI + ((brow) * ASTR + kk + bcolg) * 2;
                uint32_t bd1 = smbase + SB_HI + ((brow + 16) * ASTR + kk + bcolg) * 2;
                LDSM_X4(bh0, bh1, bh2, bh3, bd0);
                LDSM_X4(bh4, bh5, bh6, bh7, bd1);
                LDSM_X4(bm0, bm1, bm2, bm3, bd0 + (SB_LO - SB_HI));
                LDSM_X4(bm4, bm5, bm6, bm7, bd1 + (SB_LO - SB_HI));
            }
#define DO_NT(mt, nt, B0, B1, BL0, BL1, A0, A1, A2_, A3, AL0, AL1, AL2, AL3)    \
            MMA_BF16(acc[mt][nt][0], acc[mt][nt][1], acc[mt][nt][2],            \
                     acc[mt][nt][3], A0, A1, A2_, A3, B0, B1);                  \
            MMA_BF16(acc[mt][nt][0], acc[mt][nt][1], acc[mt][nt][2],            \
                     acc[mt][nt][3], A0, A1, A2_, A3, BL0, BL1);                \
            MMA_BF16(acc[mt][nt][0], acc[mt][nt][1], acc[mt][nt][2],            \
                     acc[mt][nt][3], AL0, AL1, AL2, AL3, B0, B1);
            DO_NT(0, 0, bh0, bh1, bm0, bm1, ah0, ah1, ah2, ah3, am0, am1, am2, am3)
            DO_NT(0, 1, bh2, bh3, bm2, bm3, ah0, ah1, ah2, ah3, am0, am1, am2, am3)
            DO_NT(0, 2, bh4, bh5, bm4, bm5, ah0, ah1, ah2, ah3, am0, am1, am2, am3)
            DO_NT(0, 3, bh6, bh7, bm6, bm7, ah0, ah1, ah2, ah3, am0, am1, am2, am3)
            DO_NT(1, 0, bh0, bh1, bm0, bm1, ah4, ah5, ah6, ah7, am4, am5, am6, am7)
            DO_NT(1, 1, bh2, bh3, bm2, bm3, ah4, ah5, ah6, ah7, am4, am5, am6, am7)
            DO_NT(1, 2, bh4, bh5, bm4, bm5, ah4, ah5, ah6, ah7, am4, am5, am6, am7)
            DO_NT(1, 3, bh6, bh7, bm6, bm7, ah4, ah5, ah6, ah7, am4, am5, am6, am7)
#undef DO_NT
        }
        __syncthreads();
    }

    // ---- epilogue
    int rq = lane >> 2, cq = (lane & 3) * 2;
#pragma unroll
    for (int mt = 0; mt < 2; mt++) {
        int r0 = bm + wm + mt * 16 + rq;
#pragma unroll
        for (int nt = 0; nt < 4; nt++) {
            int c0 = wn + nt * 8 + cq;
            float s0 = s_sc[c0], s1 = s_sc[c0 + 1];
            float t0 = s_sb[c0], t1 = s_sb[c0 + 1];
            float v0 = acc[mt][nt][0] * s0 + t0;
            float v1 = acc[mt][nt][1] * s1 + t1;
            float v2 = acc[mt][nt][2] * s0 + t0;
            float v3 = acc[mt][nt][3] * s1 + t1;
            if (do_relu) {
                v0 = fmaxf(v0, 0.f); v1 = fmaxf(v1, 0.f);
                v2 = fmaxf(v2, 0.f); v3 = fmaxf(v3, 0.f);
            }
            if (Chi) {
                unsigned short h0, h1, h2, h3, l0, l1, l2, l3;
                split_bf16(v0, h0, l0); split_bf16(v1, h1, l1);
                split_bf16(v2, h2, l2); split_bf16(v3, h3, l3);
                if (r0 < M) {
                    *(uint32_t*)(Chi + (size_t)r0 * N + bn + c0) =
                        (uint32_t)h0 | ((uint32_t)h1 << 16);
                    *(uint32_t*)(Clo + (size_t)r0 * N + bn + c0) =
                        (uint32_t)l0 | ((uint32_t)l1 << 16);
                }
                if (r0 + 8 < M) {
                    *(uint32_t*)(Chi + (size_t)(r0 + 8) * N + bn + c0) =
                        (uint32_t)h2 | ((uint32_t)h3 << 16);
                    *(uint32_t*)(Clo + (size_t)(r0 + 8) * N + bn + c0) =
                        (uint32_t)l2 | ((uint32_t)l3 << 16);
                }
            } else {
                if (r0 < M)
                    *(float2*)(Cf + (size_t)r0 * N + bn + c0) =
                        make_float2(v0, v1);
                if (r0 + 8 < M)
                    *(float2*)(Cf + (size_t)(r0 + 8) * N + bn + c0) =
                        make_float2(v2, v3);
            }
        }
    }
}

// ---------------------------------------------------------------------------
// fp32-A GEMM (vn path only; small). C = act(bn((al*A + A2) @ W + b))
// Same tiling; converts A in-kernel.
// ---------------------------------------------------------------------------
__global__ void __launch_bounds__(256)
gemm_mma_k(const float* __restrict__ A, const float* __restrict__ A2,
           const __nv_bfloat16* __restrict__ Bhi_g,
           const __nv_bfloat16* __restrict__ Blo_g,
           const float* __restrict__ lin_b,
           const float* __restrict__ bng, const float* __restrict__ bnb,
           const float* __restrict__ bnm, const float* __restrict__ bnv,
           float* __restrict__ C, int M, int N, int K, int do_relu) {
    extern __shared__ char dsm[];
    __shared__ float s_sc[64], s_sb[64];

    int tid = threadIdx.x;
    int lane = tid & 31, wid = tid >> 5;
    int bm = blockIdx.x * 128;
    int bn = blockIdx.y * 64;

    if (tid < 64) {
        int col = bn + tid;
        float s = bng[col] * rsqrtf(bnv[col] + 1e-5f);
        s_sc[tid] = s;
        s_sb[tid] = (lin_b[col] - bnm[col]) * s + bnb[col];
    }

    uint32_t smbase = cvta_s(dsm);
    int wm = (wid >> 1) * 32;
    int wn = (wid & 1) * 32;

    float acc[2][4][4];
#pragma unroll
    for (int a = 0; a < 2; a++)
#pragma unroll
        for (int b = 0; b < 4; b++)
#pragma unroll
            for (int q = 0; q < 4; q++) acc[a][b][q] = 0.f;

    int r8 = lane & 7, g = lane >> 3;
    int arow = wm + ((g & 1) << 3) + r8;
    int acolg = (g >> 1) << 3;
    int brow = wn + ((g >> 1) << 3) + r8;
    int bcolg = (g & 1) << 3;

    int nch = K >> 6;
    for (int ch = 0; ch < nch; ch++) {
        int cc = ch << 6;
        for (int i = tid; i < 2048; i += 256) {
            int row = i >> 4, c4 = (i & 15) << 2;
            float4 v = make_float4(0.f, 0.f, 0.f, 0.f);
            if (bm + row < M) {
                v = *(const float4*)(A + (size_t)(bm + row) * K + cc + c4);
                if (A2) {
                    float4 w = *(const float4*)(A2 + (size_t)(bm + row) * K + cc + c4);
                    v.x += w.x; v.y += w.y; v.z += w.z; v.w += w.w;
                }
            }
            unsigned short h0, h1, h2, h3, l0, l1, l2, l3;
            split_bf16(v.x, h0, l0); split_bf16(v.y, h1, l1);
            split_bf16(v.z, h2, l2); split_bf16(v.w, h3, l3);
            int off = (row * ASTR + c4) * 2;
            *(uint2*)(dsm + SA_HI + off) = make_uint2(
                (uint32_t)h0 | ((uint32_t)h1 << 16),
                (uint32_t)h2 | ((uint32_t)h3 << 16));
            *(uint2*)(dsm + SA_LO + off) = make_uint2(
                (uint32_t)l0 | ((uint32_t)l1 << 16),
                (uint32_t)l2 | ((uint32_t)l3 << 16));
        }
        for (int i = tid; i < 512; i += 256) {
            int row = i >> 3, c8 = (i & 7) << 3;
            uint4 vh = *(const uint4*)(Bhi_g + (size_t)(bn + row) * K + cc + c8);
            uint4 vl = *(const uint4*)(Blo_g + (size_t)(bn + row) * K + cc + c8);
            int off = (row * ASTR + c8) * 2;
            *(uint4*)(dsm + SB_HI + off) = vh;
            *(uint4*)(dsm + SB_LO + off) = vl;
        }
        __syncthreads();

#pragma unroll
        for (int ks = 0; ks < 4; ks++) {
            int kk = ks << 4;
            uint32_t ah0, ah1, ah2, ah3, ah4, ah5, ah6, ah7;
            uint32_t am0, am1, am2, am3, am4, am5, am6, am7;
            uint32_t bh0, bh1, bh2, bh3, bh4, bh5, bh6, bh7;
            uint32_t bm0, bm1, bm2, bm3, bm4, bm5, bm6, bm7;
            {
                uint32_t ad0 = smbase + SA_HI + ((arow) * ASTR + kk + acolg) * 2;
                uint32_t ad1 = smbase + SA_HI + ((arow + 16) * ASTR + kk + acolg) * 2;
                LDSM_X4(ah0, ah1, ah2, ah3, ad0);
                LDSM_X4(ah4, ah5, ah6, ah7, ad1);
                LDSM_X4(am0, am1, am2, am3, ad0 + (SA_LO - SA_HI));
                LDSM_X4(am4, am5, am6, am7, ad1 + (SA_LO - SA_HI));
                uint32_t bd0 = smbase + SB_HI + ((brow) * ASTR + kk + bcolg) * 2;
                uint32_t bd1 = smbase + SB_HI + ((brow + 16) * ASTR + kk + bcolg) * 2;
                LDSM_X4(bh0, bh1, bh2, bh3, bd0);
                LDSM_X4(bh4, bh5, bh6, bh7, bd1);
                LDSM_X4(bm0, bm1, bm2, bm3, bd0 + (SB_LO - SB_HI));
                LDSM_X4(bm4, bm5, bm6, bm7, bd1 + (SB_LO - SB_HI));
            }
#define DO_NT(mt, nt, B0, B1, BL0, BL1, A0, A1, A2_, A3, AL0, AL1, AL2, AL3)    \
            MMA_BF16(acc[mt][nt][0], acc[mt][nt][1], acc[mt][nt][2],            \
                     acc[mt][nt][3], A0, A1, A2_, A3, B0, B1);                  \
            MMA_BF16(acc[mt][nt][0], acc[mt][nt][1], acc[mt][nt][2],            \
                     acc[mt][nt][3], A0, A1, A2_, A3, BL0, BL1);                \
            MMA_BF16(acc[mt][nt][0], acc[mt][nt][1], acc[mt][nt][2],            \
                     acc[mt][nt][3], AL0, AL1, AL2, AL3, B0, B1);
            DO_NT(0, 0, bh0, bh1, bm0, bm1, ah0, ah1, ah2, ah3, am0, am1, am2, am3)
            DO_NT(0, 1, bh2, bh3, bm2, bm3, ah0, ah1, ah2, ah3, am0, am1, am2, am3)
            DO_NT(0, 2, bh4, bh5, bm4, bm5, ah0, ah1, ah2, ah3, am0, am1, am2, am3)
            DO_NT(0, 3, bh6, bh7, bm6, bm7, ah0, ah1, ah2, ah3, am0, am1, am2, am3)
            DO_NT(1, 0, bh0, bh1, bm0, bm1, ah4, ah5, ah6, ah7, am4, am5, am6, am7)
            DO_NT(1, 1, bh2, bh3, bm2, bm3, ah4, ah5, ah6, ah7, am4, am5, am6, am7)
            DO_NT(1, 2, bh4, bh5, bm4, bm5, ah4, ah5, ah6, ah7, am4, am5, am6, am7)
            DO_NT(1, 3, bh6, bh7, bm6, bm7, ah4, ah5, ah6, ah7, am4, am5, am6, am7)
#undef DO_NT
        }
        __syncthreads();
    }

    int rq = lane >> 2, cq = (lane & 3) * 2;
#pragma unroll
    for (int mt = 0; mt < 2; mt++) {
        int r0 = bm + wm + mt * 16 + rq;
#pragma unroll
        for (int nt = 0; nt < 4; nt++) {
            int c0 = wn + nt * 8 + cq;
            float s0 = s_sc[c0], s1 = s_sc[c0 + 1];
            float t0 = s_sb[c0], t1 = s_sb[c0 + 1];
            float v0 = acc[mt][nt][0] * s0 + t0;
            float v1 = acc[mt][nt][1] * s1 + t1;
            float v2 = acc[mt][nt][2] * s0 + t0;
            float v3 = acc[mt][nt][3] * s1 + t1;
            if (do_relu) {
                v0 = fmaxf(v0, 0.f); v1 = fmaxf(v1, 0.f);
                v2 = fmaxf(v2, 0.f); v3 = fmaxf(v3, 0.f);
            }
            if (r0 < M)
                *(float2*)(C + (size_t)r0 * N + bn + c0) = make_float2(v0, v1);
            if (r0 + 8 < M)
                *(float2*)(C + (size_t)(r0 + 8) * N + bn + c0) = make_float2(v2, v3);
        }
    }
}

// ---------------------------------------------------------------------------
// Host driver
// ---------------------------------------------------------------------------
extern "C" void kernel_launch(void* const* d_in, const int* in_sizes, int n_in,
                              void* d_out, int out_size) {
    const int*   x_atom  = (const int*)d_in[0];
    const int*   ei      = (const int*)d_in[1];
    const int*   ea      = (const int*)d_in[2];
    const int*   batch   = (const int*)d_in[3];
    const float* atomemb = (const float*)d_in[4];
    const float* vn0     = (const float*)d_in[5];
    const float* bond    = (const float*)d_in[6];
    const float* eps     = (const float*)d_in[7];
    const float* W1      = (const float*)d_in[8];
    const float* b1      = (const float*)d_in[9];
    const float* bn1g    = (const float*)d_in[10];
    const float* bn1b    = (const float*)d_in[11];
    const float* bn1m    = (const float*)d_in[12];
    const float* bn1v    = (const float*)d_in[13];
    const float* W2      = (const float*)d_in[14];
    const float* b2      = (const float*)d_in[15];
    const float* bng     = (const float*)d_in[16];
    const float* bnb     = (const float*)d_in[17];
    const float* bnm     = (const float*)d_in[18];
    const float* bnv     = (const float*)d_in[19];
    const float* vnW1    = (const float*)d_in[20];
    const float* vnb1    = (const float*)d_in[21];
    const float* vbn1g   = (const float*)d_in[22];
    const float* vbn1b   = (const float*)d_in[23];
    const float* vbn1m   = (const float*)d_in[24];
    const float* vbn1v   = (const float*)d_in[25];
    const float* vnW2    = (const float*)d_in[26];
    const float* vnb2    = (const float*)d_in[27];
    const float* vbn2g   = (const float*)d_in[28];
    const float* vbn2b   = (const float*)d_in[29];
    const float* vbn2m   = (const float*)d_in[30];
    const float* vbn2v   = (const float*)d_in[31];

    int n = in_sizes[3];
    int ecnt = in_sizes[1] / 2;

    float *h, *vn, *gsum, *vt, *cb;
    __nv_bfloat16 *zhi, *zlo, *thi, *tlo, *Bhi, *Blo;
    int *cnt, *off, *cur, *csrs, *csrc;
    cudaGetSymbolAddress((void**)&h, g_h);
    cudaGetSymbolAddress((void**)&zhi, g_zhi);
    cudaGetSymbolAddress((void**)&zlo, g_zlo);
    cudaGetSymbolAddress((void**)&thi, g_thi);
    cudaGetSymbolAddress((void**)&tlo, g_tlo);
    cudaGetSymbolAddress((void**)&vn, g_vn);
    cudaGetSymbolAddress((void**)&gsum, g_gsum);
    cudaGetSymbolAddress((void**)&vt, g_vt);
    cudaGetSymbolAddress((void**)&cb, g_cb);
    cudaGetSymbolAddress((void**)&cnt, g_cnt);
    cudaGetSymbolAddress((void**)&off, g_off);
    cudaGetSymbolAddress((void**)&cur, g_cur);
    cudaGetSymbolAddress((void**)&csrs, g_csrs);
    cudaGetSymbolAddress((void**)&csrc, g_csrc);
    cudaGetSymbolAddress((void**)&Bhi, g_Bhi);
    cudaGetSymbolAddress((void**)&Blo, g_Blo);

    cudaFuncSetAttribute(gemm_bf16_k, cudaFuncAttributeMaxDynamicSharedMemorySize,
                         SM_TOT);
    cudaFuncSetAttribute(gemm_mma_k, cudaFuncAttributeMaxDynamicSharedMemorySize,
                         SM_TOT);

    const int WSLOT = 32768;
    int nThreads = 256;
    int gridND = (n * 32 + nThreads - 1) / nThreads;
    int gridE = (ecnt + 255) / 256;

    // One-shot preprocessing
    preproc_all_k<<<(10 * 32768 + 255) / 256, 256>>>(W1, W2, vnW1, vnW2, Bhi, Blo);
    combo_tbl_k<<<(LL * 1000 * 32 + 255) / 256, 256>>>(bond, cb);
    cnt_zero_k<<<(n + 255) / 256, 256>>>(cnt, n);
    count_k<<<gridE, 256>>>(ei, cnt, ecnt);
    scan_k<<<1, 1024>>>(cnt, off, cur, n, ecnt);
    scatter_k<<<gridE, 256>>>(ei, ea, cur, csrs, csrc, ecnt);

    atom_encode_k<<<gridND, nThreads>>>(x_atom, atomemb, h, n);
    vn_init_k<<<(GG * 32 + nThreads - 1) / nThreads, nThreads>>>(vn0, vn);

    int gridM = (n + 127) / 128;
    for (int l = 0; l < LL; l++) {
        int dosum = (l < LL - 1) ? 1 : 0;
        if (dosum)
            gsum_zero_k<<<(GG * 32 + 255) / 256, 256>>>(gsum);
        add_vn_k<<<gridND, nThreads>>>(h, vn, batch, gsum, n, dosum);
        edge_csr_k<<<gridND, nThreads>>>(off, csrs, csrc,
                                         cb + (size_t)l * 1000 * DD, h,
                                         eps + l, zhi, zlo, n);

        // GEMM1: t = relu(bn1(z @ W1 + b1)) -> bf16 hi/lo   [n,256]
        {
            dim3 g(gridM, 4);
            gemm_bf16_k<<<g, 256, SM_TOT>>>(
                zhi, zlo,
                Bhi + (size_t)l * WSLOT, Blo + (size_t)l * WSLOT,
                b1 + l * 2 * DD, bn1g + l * 2 * DD, bn1b + l * 2 * DD,
                bn1m + l * 2 * DD, bn1v + l * 2 * DD,
                nullptr, thi, tlo, n, 256, 128, 1);
        }
        // GEMM2: hn = bn(t @ W2 + b2) (+relu if l<L-1) -> f32
        {
            float* outp = (l == LL - 1) ? (float*)d_out : h;
            dim3 g(gridM, 2);
            gemm_bf16_k<<<g, 256, SM_TOT>>>(
                thi, tlo,
                Bhi + (size_t)(3 + l) * WSLOT, Blo + (size_t)(3 + l) * WSLOT,
                b2 + l * DD, bng + l * DD, bnb + l * DD, bnm + l * DD,
                bnv + l * DD,
                outp, nullptr, nullptr, n, 128, 256, (l < LL - 1) ? 1 : 0);
        }
        if (l < LL - 1) {
            dim3 g1(GG / 128, 4);
            gemm_mma_k<<<g1, 256, SM_TOT>>>(
                vn, gsum,
                Bhi + (size_t)(6 + l) * WSLOT, Blo + (size_t)(6 + l) * WSLOT,
                vnb1 + l * 2 * DD, vbn1g + l * 2 * DD, vbn1b + l * 2 * DD,
                vbn1m + l * 2 * DD, vbn1v + l * 2 * DD,
                vt, GG, 256, 128, 1);
            dim3 g2(GG / 128, 2);
            gemm_mma_k<<<g2, 256, SM_TOT>>>(
                vt, nullptr,
                Bhi + (size_t)(8 + l) * WSLOT, Blo + (size_t)(8 + l) * WSLOT,
                vnb2 + l * DD, vbn2g + l * DD, vbn2b + l * DD,
                vbn2m + l * DD, vbn2v + l * DD,
                vn, GG, 128, 256, 1);
        }
    }
}

// round 6
// speedup vs baseline: 1.8494x; 1.0874x over previous
#include <cuda_runtime.h>
#include <cuda_bf16.h>
#include <cstdint>

#define MAXN 50000
#define MAXE 800000
#define GG   1024
#define DD   128
#define LL   3

// ---------------------------------------------------------------------------
// Static scratch
// ---------------------------------------------------------------------------
__device__ float g_h[MAXN * DD];
__device__ __nv_bfloat16 g_zhi[MAXN * DD];
__device__ __nv_bfloat16 g_zlo[MAXN * DD];
__device__ __nv_bfloat16 g_thi[MAXN * 2 * DD];
__device__ __nv_bfloat16 g_tlo[MAXN * 2 * DD];
__device__ float g_vn[GG * DD];
__device__ float g_gsum[GG * DD];
__device__ __nv_bfloat16 g_vthi[GG * 2 * DD];
__device__ __nv_bfloat16 g_vtlo[GG * 2 * DD];
__device__ float g_cb[LL * 1000 * DD];
__device__ int   g_cnt[MAXN];
__device__ int   g_off[MAXN + 1];
__device__ int   g_cur[MAXN];
__device__ int   g_csrs[MAXE];
__device__ int   g_csrc[MAXE];
// Preconverted weights: B^T [N][K] bf16 hi/lo. 10 slots of 32768:
// W1 l0..2, W2 l0..2, vn1 l0..1, vn2 l0..1
__device__ __nv_bfloat16 g_Bhi[10 * 32768];
__device__ __nv_bfloat16 g_Blo[10 * 32768];

// ---------------------------------------------------------------------------
// PTX helpers
// ---------------------------------------------------------------------------
__device__ __forceinline__ uint32_t cvta_s(const void* p) {
    uint32_t a;
    asm("{ .reg .u64 t; cvta.to.shared.u64 t, %1; cvt.u32.u64 %0, t; }"
        : "=r"(a) : "l"(p));
    return a;
}
#define LDSM_X4(r0, r1, r2, r3, addr)                                          \
    asm volatile("ldmatrix.sync.aligned.m8n8.x4.shared.b16 {%0,%1,%2,%3}, [%4];"\
                 : "=r"(r0), "=r"(r1), "=r"(r2), "=r"(r3) : "r"(addr))
#define MMA_BF16(d0, d1, d2, d3, a0, a1, a2, a3, b0, b1)                       \
    asm volatile("mma.sync.aligned.m16n8k16.row.col.f32.bf16.bf16.f32 "        \
                 "{%0,%1,%2,%3}, {%4,%5,%6,%7}, {%8,%9}, {%0,%1,%2,%3};"       \
                 : "+f"(d0), "+f"(d1), "+f"(d2), "+f"(d3)                      \
                 : "r"(a0), "r"(a1), "r"(a2), "r"(a3), "r"(b0), "r"(b1))

__device__ __forceinline__ void split_bf16(float v, unsigned short& hi,
                                           unsigned short& lo) {
    __nv_bfloat16 h = __float2bfloat16_rn(v);
    hi = __bfloat16_as_ushort(h);
    lo = __bfloat16_as_ushort(__float2bfloat16_rn(v - __bfloat162float(h)));
}

// ---------------------------------------------------------------------------
// Mega-fused preprocessing
// ---------------------------------------------------------------------------
__global__ void fused_pre_k(
    const float* __restrict__ W1, const float* __restrict__ W2,
    const float* __restrict__ vnW1, const float* __restrict__ vnW2,
    __nv_bfloat16* __restrict__ Bhi, __nv_bfloat16* __restrict__ Blo,
    const float* __restrict__ bond, float* __restrict__ cb,
    int* __restrict__ cnt, float* __restrict__ gsum,
    const int* __restrict__ xa, const float* __restrict__ emb,
    float* __restrict__ h,
    const float* __restrict__ v0, float* __restrict__ vn,
    int n, int c1, int c2, int c3, int c4b, int c5) {
    int blk = blockIdx.x;
    int tid = threadIdx.x;
    if (blk < c1) {
        int idx = blk * 256 + tid;
        if (idx < 10 * 32768) {
            int slot = idx >> 15;
            int r = idx & 32767;
            const float* W;
            int Nd;
            if (slot < 3)      { W = W1 + (size_t)slot * 32768;         Nd = 256; }
            else if (slot < 6) { W = W2 + (size_t)(slot - 3) * 32768;   Nd = 128; }
            else if (slot < 8) { W = vnW1 + (size_t)(slot - 6) * 32768; Nd = 256; }
            else               { W = vnW2 + (size_t)(slot - 8) * 32768; Nd = 128; }
            int Kd = 32768 / Nd;
            int k = r / Nd, nn = r % Nd;
            unsigned short hi, lo;
            split_bf16(W[r], hi, lo);
            size_t o = (size_t)slot * 32768 + (size_t)nn * Kd + k;
            Bhi[o] = __ushort_as_bfloat16(hi);
            Blo[o] = __ushort_as_bfloat16(lo);
        }
    } else if (blk < c2) {
        int idx = (blk - c1) * 256 + tid;
        if (idx < LL * 1000 * 32) {
            int cc4 = (idx & 31) << 2;
            int i = (idx >> 5) % 1000;
            int l = (idx >> 5) / 1000;
            int f0 = i / 100, f1 = (i / 10) % 10, f2 = i % 10;
            float4 a = *(const float4*)(bond + ((size_t)(l * 3 + 0) * 10 + f0) * DD + cc4);
            float4 b = *(const float4*)(bond + ((size_t)(l * 3 + 1) * 10 + f1) * DD + cc4);
            float4 c = *(const float4*)(bond + ((size_t)(l * 3 + 2) * 10 + f2) * DD + cc4);
            float4 o;
            o.x = a.x + b.x + c.x; o.y = a.y + b.y + c.y;
            o.z = a.z + b.z + c.z; o.w = a.w + b.w + c.w;
            *(float4*)(cb + ((size_t)(l * 1000 + i)) * DD + cc4) = o;
        }
    } else if (blk < c3) {
        int i = (blk - c2) * 256 + tid;
        if (i < n) cnt[i] = 0;
    } else if (blk < c4b) {
        int i = (blk - c3) * 256 + tid;
        if (i < GG * 32)
            *(float4*)(gsum + i * 4) = make_float4(0.f, 0.f, 0.f, 0.f);
    } else if (blk < c5) {
        int idx = (blk - c4b) * 256 + tid;
        if (idx < n * 32) {
            int node = idx >> 5;
            int cc4 = (idx & 31) << 2;
            float4 s = make_float4(0.f, 0.f, 0.f, 0.f);
#pragma unroll
            for (int f = 0; f < 9; f++) {
                int v = xa[node * 9 + f];
                float4 e = *(const float4*)(emb + (f * 100 + v) * DD + cc4);
                s.x += e.x; s.y += e.y; s.z += e.z; s.w += e.w;
            }
            *(float4*)(h + node * DD + cc4) = s;
        }
    } else {
        int idx = (blk - c5) * 256 + tid;
        if (idx < GG * 32) {
            int cc4 = (idx & 31) << 2;
            *(float4*)(vn + idx * 4) = *(const float4*)(v0 + cc4);
        }
    }
}

// ---------------------------------------------------------------------------
// CSR build
// ---------------------------------------------------------------------------
__global__ void count_k(const int* __restrict__ ei, int* __restrict__ cnt,
                        int ecnt) {
    int j = blockIdx.x * blockDim.x + threadIdx.x;
    if (j < ecnt) atomicAdd(&cnt[ei[ecnt + j]], 1);
}
__global__ void scan_k(const int* __restrict__ cnt, int* __restrict__ off,
                       int* __restrict__ cur, int n, int ecnt) {
    __shared__ int part[1024];
    int t = threadIdx.x;
    int chunk = (n + 1023) >> 10;
    int beg = t * chunk;
    int end = min(beg + chunk, n);
    int s = 0;
    for (int i = beg; i < end; i++) s += cnt[i];
    part[t] = s;
    __syncthreads();
    for (int d = 1; d < 1024; d <<= 1) {
        int v = (t >= d) ? part[t - d] : 0;
        __syncthreads();
        if (t >= d) part[t] += v;
        __syncthreads();
    }
    int run = (t == 0) ? 0 : part[t - 1];
    for (int i = beg; i < end; i++) {
        off[i] = run;
        cur[i] = run;
        run += cnt[i];
    }
    if (t == 0) off[n] = ecnt;
}
__global__ void scatter_k(const int* __restrict__ ei, const int* __restrict__ ea,
                          int* __restrict__ cur, int* __restrict__ csrs,
                          int* __restrict__ csrc, int ecnt) {
    int j = blockIdx.x * blockDim.x + threadIdx.x;
    if (j >= ecnt) return;
    int dst = ei[ecnt + j];
    int pos = atomicAdd(&cur[dst], 1);
    csrs[pos] = ei[j];
    csrc[pos] = ea[j * 3] * 100 + ea[j * 3 + 1] * 10 + ea[j * 3 + 2];
}

// ---------------------------------------------------------------------------
// h += vn[batch]; optionally gsum[batch] += h (post-update)
// ---------------------------------------------------------------------------
__global__ void add_vn_k(float* __restrict__ h, const float* __restrict__ vn,
                         const int* __restrict__ batch,
                         float* __restrict__ gsum, int n, int dosum) {
    int idx = blockIdx.x * blockDim.x + threadIdx.x;
    if (idx >= n * 32) return;
    int node = idx >> 5;
    int c4 = (idx & 31) << 2;
    int g = batch[node];
    float4 hv = *(float4*)(h + idx * 4);
    float4 vv = *(const float4*)(vn + g * DD + c4);
    hv.x += vv.x; hv.y += vv.y; hv.z += vv.z; hv.w += vv.w;
    *(float4*)(h + idx * 4) = hv;
    if (dosum) {
        float* p = gsum + g * DD + c4;
        asm volatile("red.global.add.v4.f32 [%0], {%1,%2,%3,%4};"
                     :: "l"(p), "f"(hv.x), "f"(hv.y), "f"(hv.z), "f"(hv.w)
                     : "memory");
    }
}

// ---------------------------------------------------------------------------
// Edge gather (CSR), 4x unrolled
// ---------------------------------------------------------------------------
__global__ void edge_csr_k(const int* __restrict__ off,
                           const int* __restrict__ csrs,
                           const int* __restrict__ csrc,
                           const float* __restrict__ cb,
                           const float* __restrict__ h,
                           const float* __restrict__ eps_p,
                           __nv_bfloat16* __restrict__ zhi,
                           __nv_bfloat16* __restrict__ zlo, int n) {
    int warp = (blockIdx.x * blockDim.x + threadIdx.x) >> 5;
    if (warp >= n) return;
    int lane = threadIdx.x & 31;
    int c4 = lane << 2;
    float4 acc = make_float4(0.f, 0.f, 0.f, 0.f);
    int beg = off[warp], end = off[warp + 1];
    const unsigned FULL = 0xffffffffu;
    for (int base = beg; base < end; base += 32) {
        int m = min(32, end - base);
        int s = 0, cm = 0;
        if (base + lane < end) {
            s = csrs[base + lane];
            cm = csrc[base + lane];
        }
        int k = 0;
        for (; k + 4 <= m; k += 4) {
            int s0 = __shfl_sync(FULL, s, k),     c0 = __shfl_sync(FULL, cm, k);
            int s1 = __shfl_sync(FULL, s, k + 1), c1 = __shfl_sync(FULL, cm, k + 1);
            int s2 = __shfl_sync(FULL, s, k + 2), c2 = __shfl_sync(FULL, cm, k + 2);
            int s3 = __shfl_sync(FULL, s, k + 3), c3 = __shfl_sync(FULL, cm, k + 3);
            float4 h0 = *(const float4*)(h + (size_t)s0 * DD + c4);
            float4 e0 = *(const float4*)(cb + (size_t)c0 * DD + c4);
            float4 h1 = *(const float4*)(h + (size_t)s1 * DD + c4);
            float4 e1 = *(const float4*)(cb + (size_t)c1 * DD + c4);
            float4 h2 = *(const float4*)(h + (size_t)s2 * DD + c4);
            float4 e2 = *(const float4*)(cb + (size_t)c2 * DD + c4);
            float4 h3 = *(const float4*)(h + (size_t)s3 * DD + c4);
            float4 e3 = *(const float4*)(cb + (size_t)c3 * DD + c4);
            acc.x += fmaxf(h0.x + e0.x, 0.f) + fmaxf(h1.x + e1.x, 0.f)
                   + fmaxf(h2.x + e2.x, 0.f) + fmaxf(h3.x + e3.x, 0.f);
            acc.y += fmaxf(h0.y + e0.y, 0.f) + fmaxf(h1.y + e1.y, 0.f)
                   + fmaxf(h2.y + e2.y, 0.f) + fmaxf(h3.y + e3.y, 0.f);
            acc.z += fmaxf(h0.z + e0.z, 0.f) + fmaxf(h1.z + e1.z, 0.f)
                   + fmaxf(h2.z + e2.z, 0.f) + fmaxf(h3.z + e3.z, 0.f);
            acc.w += fmaxf(h0.w + e0.w, 0.f) + fmaxf(h1.w + e1.w, 0.f)
                   + fmaxf(h2.w + e2.w, 0.f) + fmaxf(h3.w + e3.w, 0.f);
        }
        for (; k < m; k++) {
            int ss = __shfl_sync(FULL, s, k);
            int cc = __shfl_sync(FULL, cm, k);
            float4 hv = *(const float4*)(h + (size_t)ss * DD + c4);
            float4 ev = *(const float4*)(cb + (size_t)cc * DD + c4);
            acc.x += fmaxf(hv.x + ev.x, 0.f);
            acc.y += fmaxf(hv.y + ev.y, 0.f);
            acc.z += fmaxf(hv.z + ev.z, 0.f);
            acc.w += fmaxf(hv.w + ev.w, 0.f);
        }
    }
    float al = 1.0f + *eps_p;
    float4 hv = *(const float4*)(h + (size_t)warp * DD + c4);
    unsigned short h0, h1, h2, h3, l0, l1, l2, l3;
    split_bf16(al * hv.x + acc.x, h0, l0);
    split_bf16(al * hv.y + acc.y, h1, l1);
    split_bf16(al * hv.z + acc.z, h2, l2);
    split_bf16(al * hv.w + acc.w, h3, l3);
    uint2 hp = make_uint2((uint32_t)h0 | ((uint32_t)h1 << 16),
                          (uint32_t)h2 | ((uint32_t)h3 << 16));
    uint2 lp = make_uint2((uint32_t)l0 | ((uint32_t)l1 << 16),
                          (uint32_t)l2 | ((uint32_t)l3 << 16));
    *(uint2*)(zhi + (size_t)warp * DD + c4) = hp;
    *(uint2*)(zlo + (size_t)warp * DD + c4) = lp;
}

// ---------------------------------------------------------------------------
// Unified GEMM with vn rider blocks
// ---------------------------------------------------------------------------
#define ASTR 72
#define SA_HI 0
#define SA_LO 18432
#define SB_HI 36864
#define SB_LO 46080
#define SM_TOT 55296

__global__ void __launch_bounds__(256)
gemm_uni_k(int gx0, int ny0, int M0,
           const __nv_bfloat16* __restrict__ A0hi,
           const __nv_bfloat16* __restrict__ A0lo,
           const __nv_bfloat16* __restrict__ B0hi,
           const __nv_bfloat16* __restrict__ B0lo,
           const float* __restrict__ lb0, const float* __restrict__ g0,
           const float* __restrict__ be0, const float* __restrict__ m0,
           const float* __restrict__ vv0,
           float* __restrict__ C0f,
           __nv_bfloat16* __restrict__ C0hi, __nv_bfloat16* __restrict__ C0lo,
           int ny1, int M1,
           const float* __restrict__ A1f, const float* __restrict__ A1f2,
           const __nv_bfloat16* __restrict__ A1hi,
           const __nv_bfloat16* __restrict__ A1lo,
           const __nv_bfloat16* __restrict__ B1hi,
           const __nv_bfloat16* __restrict__ B1lo,
           const float* __restrict__ lb1, const float* __restrict__ g1,
           const float* __restrict__ be1, const float* __restrict__ m1,
           const float* __restrict__ vv1,
           float* __restrict__ C1f,
           __nv_bfloat16* __restrict__ C1hi, __nv_bfloat16* __restrict__ C1lo,
           float4* __restrict__ zbuf, int zcnt4,
           int N, int K, int do_relu) {
    extern __shared__ char dsm[];
    __shared__ float s_sc[64], s_sb[64];

    int tid = threadIdx.x;
    int lane = tid & 31, wid = tid >> 5;

    int q = blockIdx.x;
    int part = 0, bx, by;
    if (q < gx0 * ny0) { bx = q / ny0; by = q % ny0; }
    else { part = 1; q -= gx0 * ny0; bx = q / ny1; by = q % ny1; }

    int M = part ? M1 : M0;
    const __nv_bfloat16* Ahi = part ? A1hi : A0hi;
    const __nv_bfloat16* Alo = part ? A1lo : A0lo;
    const __nv_bfloat16* Bh  = part ? B1hi : B0hi;
    const __nv_bfloat16* Bl  = part ? B1lo : B0lo;
    const float* lb = part ? lb1 : lb0;
    const float* gg = part ? g1 : g0;
    const float* bbp = part ? be1 : be0;
    const float* mmp = part ? m1 : m0;
    const float* vvp = part ? vv1 : vv0;
    float* Cf = part ? C1f : C0f;
    __nv_bfloat16* Chi = part ? C1hi : C0hi;
    __nv_bfloat16* Clo = part ? C1lo : C0lo;
    const float* Af  = part ? A1f  : (const float*)0;
    const float* Af2 = part ? A1f2 : (const float*)0;
    bool fp32A = (part && Af);

    int bm = bx * 128;
    int bn = by * 64;

    if (part == 1 && zbuf) {
        int rb = gridDim.x - gx0 * ny0;
        int rid = bx * ny1 + by;
        for (int i = rid * 256 + tid; i < zcnt4; i += rb * 256)
            zbuf[i] = make_float4(0.f, 0.f, 0.f, 0.f);
    }

    if (tid < 64) {
        int col = bn + tid;
        float s = gg[col] * rsqrtf(vvp[col] + 1e-5f);
        s_sc[tid] = s;
        s_sb[tid] = (lb[col] - mmp[col]) * s + bbp[col];
    }

    uint32_t smbase = cvta_s(dsm);
    int wm = (wid >> 1) * 32;
    int wn = (wid & 1) * 32;

    float acc[2][4][4];
#pragma unroll
    for (int a = 0; a < 2; a++)
#pragma unroll
        for (int b = 0; b < 4; b++)
#pragma unroll
            for (int qq = 0; qq < 4; qq++) acc[a][b][qq] = 0.f;

    int r8 = lane & 7, g = lane >> 3;
    int arow = wm + ((g & 1) << 3) + r8;
    int acolg = (g >> 1) << 3;
    int brow = wn + ((g >> 1) << 3) + r8;
    int bcolg = (g & 1) << 3;

    int nch = K >> 6;
    for (int ch = 0; ch < nch; ch++) {
        int cc = ch << 6;
        if (!fp32A) {
            for (int i = tid; i < 1024; i += 256) {
                int row = i >> 3, c8 = (i & 7) << 3;
                uint4 vh = make_uint4(0u, 0u, 0u, 0u), vl = vh;
                if (bm + row < M) {
                    vh = *(const uint4*)(Ahi + (size_t)(bm + row) * K + cc + c8);
                    vl = *(const uint4*)(Alo + (size_t)(bm + row) * K + cc + c8);
                }
                int off = (row * ASTR + c8) * 2;
                *(uint4*)(dsm + SA_HI + off) = vh;
                *(uint4*)(dsm + SA_LO + off) = vl;
            }
        } else {
            for (int i = tid; i < 2048; i += 256) {
                int row = i >> 4, c4 = (i & 15) << 2;
                float4 v = make_float4(0.f, 0.f, 0.f, 0.f);
                if (bm + row < M) {
                    v = *(const float4*)(Af + (size_t)(bm + row) * K + cc + c4);
                    float4 w = *(const float4*)(Af2 + (size_t)(bm + row) * K + cc + c4);
                    v.x += w.x; v.y += w.y; v.z += w.z; v.w += w.w;
                }
                unsigned short h0, h1, h2, h3, l0, l1, l2, l3;
                split_bf16(v.x, h0, l0); split_bf16(v.y, h1, l1);
                split_bf16(v.z, h2, l2); split_bf16(v.w, h3, l3);
                int off = (row * ASTR + c4) * 2;
                *(uint2*)(dsm + SA_HI + off) = make_uint2(
                    (uint32_t)h0 | ((uint32_t)h1 << 16),
                    (uint32_t)h2 | ((uint32_t)h3 << 16));
                *(uint2*)(dsm + SA_LO + off) = make_uint2(
                    (uint32_t)l0 | ((uint32_t)l1 << 16),
                    (uint32_t)l2 | ((uint32_t)l3 << 16));
            }
        }
        for (int i = tid; i < 512; i += 256) {
            int row = i >> 3, c8 = (i & 7) << 3;
            uint4 vh = *(const uint4*)(Bh + (size_t)(bn + row) * K + cc + c8);
            uint4 vl = *(const uint4*)(Bl + (size_t)(bn + row) * K + cc + c8);
            int off = (row * ASTR + c8) * 2;
            *(uint4*)(dsm + SB_HI + off) = vh;
            *(uint4*)(dsm + SB_LO + off) = vl;
        }
        __syncthreads();

#pragma unroll
        for (int ks = 0; ks < 4; ks++) {
            int kk = ks << 4;
            uint32_t ah0, ah1, ah2, ah3, ah4, ah5, ah6, ah7;
            uint32_t am0, am1, am2, am3, am4, am5, am6, am7;
            uint32_t bh0, bh1, bh2, bh3, bh4, bh5, bh6, bh7;
            uint32_t bm0, bm1, bm2, bm3, bm4, bm5, bm6, bm7;
            {
                uint32_t ad0 = smbase + SA_HI + ((arow) * ASTR + kk + acolg) * 2;
                uint32_t ad1 = smbase + SA_HI + ((arow + 16) * ASTR + kk + acolg) * 2;
                LDSM_X4(ah0, ah1, ah2, ah3, ad0);
                LDSM_X4(ah4, ah5, ah6, ah7, ad1);
                LDSM_X4(am0, am1, am2, am3, ad0 + (SA_LO - SA_HI));
                LDSM_X4(am4, am5, am6, am7, ad1 + (SA_LO - SA_HI));
                uint32_t bd0 = smbase + SB_HI + ((brow) * ASTR + kk + bcolg) * 2;
                uint32_t bd1 = smbase + SB_HI + ((brow + 16) * ASTR + kk + bcolg) * 2;
                LDSM_X4(bh0, bh1, bh2, bh3, bd0);
                LDSM_X4(bh4, bh5, bh6, bh7, bd1);
                LDSM_X4(bm0, bm1, bm2, bm3, bd0 + (SB_LO - SB_HI));
                LDSM_X4(bm4, bm5, bm6, bm7, bd1 + (SB_LO - SB_HI));
            }
#define DO_NT(mt, nt, B0, B1, BL0, BL1, A0, A1, A2_, A3, AL0, AL1, AL2, AL3)    \
            MMA_BF16(acc[mt][nt][0], acc[mt][nt][1], acc[mt][nt][2],            \
                     acc[mt][nt][3], A0, A1, A2_, A3, B0, B1);                  \
            MMA_BF16(acc[mt][nt][0], acc[mt][nt][1], acc[mt][nt][2],            \
                     acc[mt][nt][3], A0, A1, A2_, A3, BL0, BL1);                \
            MMA_BF16(acc[mt][nt][0], acc[mt][nt][1], acc[mt][nt][2],            \
                     acc[mt][nt][3], AL0, AL1, AL2, AL3, B0, B1);
            DO_NT(0, 0, bh0, bh1, bm0, bm1, ah0, ah1, ah2, ah3, am0, am1, am2, am3)
            DO_NT(0, 1, bh2, bh3, bm2, bm3, ah0, ah1, ah2, ah3, am0, am1, am2, am3)
            DO_NT(0, 2, bh4, bh5, bm4, bm5, ah0, ah1, ah2, ah3, am0, am1, am2, am3)
            DO_NT(0, 3, bh6, bh7, bm6, bm7, ah0, ah1, ah2, ah3, am0, am1, am2, am3)
            DO_NT(1, 0, bh0, bh1, bm0, bm1, ah4, ah5, ah6, ah7, am4, am5, am6, am7)
            DO_NT(1, 1, bh2, bh3, bm2, bm3, ah4, ah5, ah6, ah7, am4, am5, am6, am7)
            DO_NT(1, 2, bh4, bh5, bm4, bm5, ah4, ah5, ah6, ah7, am4, am5, am6, am7)
            DO_NT(1, 3, bh6, bh7, bm6, bm7, ah4, ah5, ah6, ah7, am4, am5, am6, am7)
#undef DO_NT
        }
        __syncthreads();
    }

    int rq = lane >> 2, cq = (lane & 3) * 2;
    bool outBF = (Chi != (__nv_bfloat16*)0);
#pragma unroll
    for (int mt = 0; mt < 2; mt++) {
        int r0 = bm + wm + mt * 16 + rq;
#pragma unroll
        for (int nt = 0; nt < 4; nt++) {
            int c0 = wn + nt * 8 + cq;
            float s0 = s_sc[c0], s1 = s_sc[c0 + 1];
            float t0 = s_sb[c0], t1 = s_sb[c0 + 1];
            float v0 = acc[mt][nt][0] * s0 + t0;
            float v1 = acc[mt][nt][1] * s1 + t1;
            float v2 = acc[mt][nt][2] * s0 + t0;
            float v3 = acc[mt][nt][3] * s1 + t1;
            if (do_relu) {
                v0 = fmaxf(v0, 0.f); v1 = fmaxf(v1, 0.f);
                v2 = fmaxf(v2, 0.f); v3 = fmaxf(v3, 0.f);
            }
            if (outBF) {
                unsigned short h0, h1, h2, h3, l0, l1, l2, l3;
                split_bf16(v0, h0, l0); split_bf16(v1, h1, l1);
                split_bf16(v2, h2, l2); split_bf16(v3, h3, l3);
                if (r0 < M) {
                    *(uint32_t*)(Chi + (size_t)r0 * N + bn + c0) =
                        (uint32_t)h0 | ((uint32_t)h1 << 16);
                    *(uint32_t*)(Clo + (size_t)r0 * N + bn + c0) =
                        (uint32_t)l0 | ((uint32_t)l1 << 16);
                }
                if (r0 + 8 < M) {
                    *(uint32_t*)(Chi + (size_t)(r0 + 8) * N + bn + c0) =
                        (uint32_t)h2 | ((uint32_t)h3 << 16);
                    *(uint32_t*)(Clo + (size_t)(r0 + 8) * N + bn + c0) =
                        (uint32_t)l2 | ((uint32_t)l3 << 16);
                }
            } else {
                if (r0 < M)
                    *(float2*)(Cf + (size_t)r0 * N + bn + c0) = make_float2(v0, v1);
                if (r0 + 8 < M)
                    *(float2*)(Cf + (size_t)(r0 + 8) * N + bn + c0) = make_float2(v2, v3);
            }
        }
    }
}

// ---------------------------------------------------------------------------
// Host driver
// ---------------------------------------------------------------------------
extern "C" void kernel_launch(void* const* d_in, const int* in_sizes, int n_in,
                              void* d_out, int out_size) {
    const int*   x_atom  = (const int*)d_in[0];
    const int*   ei      = (const int*)d_in[1];
    const int*   ea      = (const int*)d_in[2];
    const int*   batch   = (const int*)d_in[3];
    const float* atomemb = (const float*)d_in[4];
    const float* vn0     = (const float*)d_in[5];
    const float* bond    = (const float*)d_in[6];
    const float* eps     = (const float*)d_in[7];
    const float* W1      = (const float*)d_in[8];
    const float* b1v     = (const float*)d_in[9];
    const float* bn1g    = (const float*)d_in[10];
    const float* bn1b    = (const float*)d_in[11];
    const float* bn1m    = (const float*)d_in[12];
    const float* bn1v    = (const float*)d_in[13];
    const float* W2      = (const float*)d_in[14];
    const float* b2v     = (const float*)d_in[15];
    const float* bng     = (const float*)d_in[16];
    const float* bnb     = (const float*)d_in[17];
    const float* bnm     = (const float*)d_in[18];
    const float* bnv     = (const float*)d_in[19];
    const float* vnW1    = (const float*)d_in[20];
    const float* vnb1    = (const float*)d_in[21];
    const float* vbn1g   = (const float*)d_in[22];
    const float* vbn1b   = (const float*)d_in[23];
    const float* vbn1m   = (const float*)d_in[24];
    const float* vbn1v   = (const float*)d_in[25];
    const float* vnW2    = (const float*)d_in[26];
    const float* vnb2    = (const float*)d_in[27];
    const float* vbn2g   = (const float*)d_in[28];
    const float* vbn2b   = (const float*)d_in[29];
    const float* vbn2m   = (const float*)d_in[30];
    const float* vbn2v   = (const float*)d_in[31];

    int n = in_sizes[3];
    int ecnt = in_sizes[1] / 2;

    float *h, *vn, *gsum, *cb;
    __nv_bfloat16 *zhi, *zlo, *thi, *tlo, *vthi, *vtlo, *Bhi, *Blo;
    int *cnt, *off, *cur, *csrs, *csrc;
    cudaGetSymbolAddress((void**)&h, g_h);
    cudaGetSymbolAddress((void**)&zhi, g_zhi);
    cudaGetSymbolAddress((void**)&zlo, g_zlo);
    cudaGetSymbolAddress((void**)&thi, g_thi);
    cudaGetSymbolAddress((void**)&tlo, g_tlo);
    cudaGetSymbolAddress((void**)&vn, g_vn);
    cudaGetSymbolAddress((void**)&gsum, g_gsum);
    cudaGetSymbolAddress((void**)&vthi, g_vthi);
    cudaGetSymbolAddress((void**)&vtlo, g_vtlo);
    cudaGetSymbolAddress((void**)&cb, g_cb);
    cudaGetSymbolAddress((void**)&cnt, g_cnt);
    cudaGetSymbolAddress((void**)&off, g_off);
    cudaGetSymbolAddress((void**)&cur, g_cur);
    cudaGetSymbolAddress((void**)&csrs, g_csrs);
    cudaGetSymbolAddress((void**)&csrc, g_csrc);
    cudaGetSymbolAddress((void**)&Bhi, g_Bhi);
    cudaGetSymbolAddress((void**)&Blo, g_Blo);

    cudaFuncSetAttribute(gemm_uni_k, cudaFuncAttributeMaxDynamicSharedMemorySize,
                         SM_TOT);

    const int WSLOT = 32768;
    int gridND = (n * 32 + 255) / 256;
    int gridE = (ecnt + 255) / 256;

    int c1 = (10 * 32768 + 255) / 256;
    int c2 = c1 + (LL * 1000 * 32 + 255) / 256;
    int c3 = c2 + (n + 255) / 256;
    int c4b = c3 + (GG * 32 + 255) / 256;
    int c5 = c4b + gridND;
    int c6 = c5 + (GG * 32 + 255) / 256;
    fused_pre_k<<<c6, 256>>>(W1, W2, vnW1, vnW2, Bhi, Blo, bond, cb,
                             cnt, gsum, x_atom, atomemb, h, vn0, vn,
                             n, c1, c2, c3, c4b, c5);
    count_k<<<gridE, 256>>>(ei, cnt, ecnt);
    scan_k<<<1, 1024>>>(cnt, off, cur, n, ecnt);
    scatter_k<<<gridE, 256>>>(ei, ea, cur, csrs, csrc, ecnt);

    int gridM = (n + 127) / 128;
    int gxv = GG / 128;
    for (int l = 0; l < LL; l++) {
        int hasVN = (l < LL - 1) ? 1 : 0;
        add_vn_k<<<gridND, 256>>>(h, vn, batch, gsum, n, hasVN);
        edge_csr_k<<<gridND, 256>>>(off, csrs, csrc,
                                    cb + (size_t)l * 1000 * DD, h,
                                    eps + l, zhi, zlo, n);
        {
            int ny0 = 4, ny1 = 4;
            int grid = gridM * ny0 + (hasVN ? gxv * ny1 : 0);
            gemm_uni_k<<<grid, 256, SM_TOT>>>(
                gridM, ny0, n,
                zhi, zlo,
                Bhi + (size_t)l * WSLOT, Blo + (size_t)l * WSLOT,
                b1v + l * 256, bn1g + l * 256, bn1b + l * 256,
                bn1m + l * 256, bn1v + l * 256,
                nullptr, thi, tlo,
                ny1, hasVN ? GG : 0,
                vn, gsum, nullptr, nullptr,
                Bhi + (size_t)(6 + l) * WSLOT, Blo + (size_t)(6 + l) * WSLOT,
                vnb1 + l * 256, vbn1g + l * 256, vbn1b + l * 256,
                vbn1m + l * 256, vbn1v + l * 256,
                nullptr, vthi, vtlo,
                nullptr, 0,
                256, 128, 1);
        }
        {
            float* outp = (l == LL - 1) ? (float*)d_out : h;
            int ny0 = 2, ny1 = 2;
            int grid = gridM * ny0 + (hasVN ? gxv * ny1 : 0);
            gemm_uni_k<<<grid, 256, SM_TOT>>>(
                gridM, ny0, n,
                thi, tlo,
                Bhi + (size_t)(3 + l) * WSLOT, Blo + (size_t)(3 + l) * WSLOT,
                b2v + l * 128, bng + l * 128, bnb + l * 128,
                bnm + l * 128, bnv + l * 128,
                outp, nullptr, nullptr,
                ny1, hasVN ? GG : 0,
                nullptr, nullptr, vthi, vtlo,
                Bhi + (size_t)(8 + l) * WSLOT, Blo + (size_t)(8 + l) * WSLOT,
                vnb2 + l * 128, vbn2g + l * 128, vbn2b + l * 128,
                vbn2m + l * 128, vbn2v + l * 128,
                vn, nullptr, nullptr,
                (l == 0) ? (float4*)gsum : nullptr, GG * 32,
                128, 256, hasVN);
        }
    }
}

// round 7
// speedup vs baseline: 1.8559x; 1.0035x over previous
#include <cuda_runtime.h>
#include <cuda_bf16.h>
#include <cstdint>

#define MAXN 50000
#define MAXE 800000
#define GG   1024
#define DD   128
#define LL   3

// ---------------------------------------------------------------------------
// Static scratch
// ---------------------------------------------------------------------------
__device__ float g_h[MAXN * DD];
__device__ __nv_bfloat16 g_zhi[MAXN * DD];
__device__ __nv_bfloat16 g_zlo[MAXN * DD];
__device__ __nv_bfloat16 g_thi[MAXN * 2 * DD];
__device__ __nv_bfloat16 g_tlo[MAXN * 2 * DD];
__device__ float g_vn[GG * DD];
__device__ float g_gsum[GG * DD];
__device__ __nv_bfloat16 g_vthi[GG * 2 * DD];
__device__ __nv_bfloat16 g_vtlo[GG * 2 * DD];
__device__ float g_cb[LL * 1000 * DD];
__device__ int   g_cnt[MAXN];
__device__ int   g_off[MAXN + 1];
__device__ int   g_cur[MAXN];
__device__ int2  g_csr[MAXE];                  // packed {src, combo}
// Preconverted weights: B^T [N][K] bf16 hi/lo. 10 slots of 32768:
// W1 l0..2, W2 l0..2, vn1 l0..1, vn2 l0..1
__device__ __nv_bfloat16 g_Bhi[10 * 32768];
__device__ __nv_bfloat16 g_Blo[10 * 32768];

// ---------------------------------------------------------------------------
// PTX helpers
// ---------------------------------------------------------------------------
__device__ __forceinline__ uint32_t cvta_s(const void* p) {
    uint32_t a;
    asm("{ .reg .u64 t; cvta.to.shared.u64 t, %1; cvt.u32.u64 %0, t; }"
        : "=r"(a) : "l"(p));
    return a;
}
#define LDSM_X4(r0, r1, r2, r3, addr)                                          \
    asm volatile("ldmatrix.sync.aligned.m8n8.x4.shared.b16 {%0,%1,%2,%3}, [%4];"\
                 : "=r"(r0), "=r"(r1), "=r"(r2), "=r"(r3) : "r"(addr))
#define MMA_BF16(d0, d1, d2, d3, a0, a1, a2, a3, b0, b1)                       \
    asm volatile("mma.sync.aligned.m16n8k16.row.col.f32.bf16.bf16.f32 "        \
                 "{%0,%1,%2,%3}, {%4,%5,%6,%7}, {%8,%9}, {%0,%1,%2,%3};"       \
                 : "+f"(d0), "+f"(d1), "+f"(d2), "+f"(d3)                      \
                 : "r"(a0), "r"(a1), "r"(a2), "r"(a3), "r"(b0), "r"(b1))
#define CP_ASYNC16(dst, src, sz)                                               \
    asm volatile("cp.async.cg.shared.global [%0], [%1], 16, %2;"               \
                 :: "r"(dst), "l"(src), "r"(sz))
#define CP_COMMIT() asm volatile("cp.async.commit_group;" ::: "memory")
#define CP_WAIT1()  asm volatile("cp.async.wait_group 1;" ::: "memory")

__device__ __forceinline__ void split_bf16(float v, unsigned short& hi,
                                           unsigned short& lo) {
    __nv_bfloat16 h = __float2bfloat16_rn(v);
    hi = __bfloat16_as_ushort(h);
    lo = __bfloat16_as_ushort(__float2bfloat16_rn(v - __bfloat162float(h)));
}

// ---------------------------------------------------------------------------
// Mega-fused preprocessing
// ---------------------------------------------------------------------------
__global__ void fused_pre_k(
    const float* __restrict__ W1, const float* __restrict__ W2,
    const float* __restrict__ vnW1, const float* __restrict__ vnW2,
    __nv_bfloat16* __restrict__ Bhi, __nv_bfloat16* __restrict__ Blo,
    const float* __restrict__ bond, float* __restrict__ cb,
    int* __restrict__ cnt, float* __restrict__ gsum,
    const int* __restrict__ xa, const float* __restrict__ emb,
    float* __restrict__ h,
    const float* __restrict__ v0, float* __restrict__ vn,
    int n, int c1, int c2, int c3, int c4b, int c5) {
    int blk = blockIdx.x;
    int tid = threadIdx.x;
    if (blk < c1) {
        int idx = blk * 256 + tid;
        if (idx < 10 * 32768) {
            int slot = idx >> 15;
            int r = idx & 32767;
            const float* W;
            int Nd;
            if (slot < 3)      { W = W1 + (size_t)slot * 32768;         Nd = 256; }
            else if (slot < 6) { W = W2 + (size_t)(slot - 3) * 32768;   Nd = 128; }
            else if (slot < 8) { W = vnW1 + (size_t)(slot - 6) * 32768; Nd = 256; }
            else               { W = vnW2 + (size_t)(slot - 8) * 32768; Nd = 128; }
            int Kd = 32768 / Nd;
            int k = r / Nd, nn = r % Nd;
            unsigned short hi, lo;
            split_bf16(W[r], hi, lo);
            size_t o = (size_t)slot * 32768 + (size_t)nn * Kd + k;
            Bhi[o] = __ushort_as_bfloat16(hi);
            Blo[o] = __ushort_as_bfloat16(lo);
        }
    } else if (blk < c2) {
        int idx = (blk - c1) * 256 + tid;
        if (idx < LL * 1000 * 32) {
            int cc4 = (idx & 31) << 2;
            int i = (idx >> 5) % 1000;
            int l = (idx >> 5) / 1000;
            int f0 = i / 100, f1 = (i / 10) % 10, f2 = i % 10;
            float4 a = *(const float4*)(bond + ((size_t)(l * 3 + 0) * 10 + f0) * DD + cc4);
            float4 b = *(const float4*)(bond + ((size_t)(l * 3 + 1) * 10 + f1) * DD + cc4);
            float4 c = *(const float4*)(bond + ((size_t)(l * 3 + 2) * 10 + f2) * DD + cc4);
            float4 o;
            o.x = a.x + b.x + c.x; o.y = a.y + b.y + c.y;
            o.z = a.z + b.z + c.z; o.w = a.w + b.w + c.w;
            *(float4*)(cb + ((size_t)(l * 1000 + i)) * DD + cc4) = o;
        }
    } else if (blk < c3) {
        int i = (blk - c2) * 256 + tid;
        if (i < n) cnt[i] = 0;
    } else if (blk < c4b) {
        int i = (blk - c3) * 256 + tid;
        if (i < GG * 32)
            *(float4*)(gsum + i * 4) = make_float4(0.f, 0.f, 0.f, 0.f);
    } else if (blk < c5) {
        int idx = (blk - c4b) * 256 + tid;
        if (idx < n * 32) {
            int node = idx >> 5;
            int cc4 = (idx & 31) << 2;
            float4 s = make_float4(0.f, 0.f, 0.f, 0.f);
#pragma unroll
            for (int f = 0; f < 9; f++) {
                int v = xa[node * 9 + f];
                float4 e = *(const float4*)(emb + (f * 100 + v) * DD + cc4);
                s.x += e.x; s.y += e.y; s.z += e.z; s.w += e.w;
            }
            *(float4*)(h + node * DD + cc4) = s;
        }
    } else {
        int idx = (blk - c5) * 256 + tid;
        if (idx < GG * 32) {
            int cc4 = (idx & 31) << 2;
            *(float4*)(vn + idx * 4) = *(const float4*)(v0 + cc4);
        }
    }
}

// ---------------------------------------------------------------------------
// CSR build
// ---------------------------------------------------------------------------
__global__ void count_k(const int* __restrict__ ei, int* __restrict__ cnt,
                        int ecnt) {
    int j = (blockIdx.x * blockDim.x + threadIdx.x) * 4;
    if (j + 3 < ecnt) {
        int4 d = *(const int4*)(ei + ecnt + j);
        atomicAdd(&cnt[d.x], 1);
        atomicAdd(&cnt[d.y], 1);
        atomicAdd(&cnt[d.z], 1);
        atomicAdd(&cnt[d.w], 1);
    } else {
        for (int q = j; q < ecnt; q++) atomicAdd(&cnt[ei[ecnt + q]], 1);
    }
}
__global__ void scan_k(const int* __restrict__ cnt, int* __restrict__ off,
                       int* __restrict__ cur, int n, int ecnt) {
    __shared__ int part[1024];
    int t = threadIdx.x;
    int chunk = (n + 1023) >> 10;
    int beg = t * chunk;
    int end = min(beg + chunk, n);
    int s = 0;
    for (int i = beg; i < end; i++) s += cnt[i];
    part[t] = s;
    __syncthreads();
    for (int d = 1; d < 1024; d <<= 1) {
        int v = (t >= d) ? part[t - d] : 0;
        __syncthreads();
        if (t >= d) part[t] += v;
        __syncthreads();
    }
    int run = (t == 0) ? 0 : part[t - 1];
    for (int i = beg; i < end; i++) {
        off[i] = run;
        cur[i] = run;
        run += cnt[i];
    }
    if (t == 0) off[n] = ecnt;
}
__global__ void scatter_k(const int* __restrict__ ei, const int* __restrict__ ea,
                          int* __restrict__ cur, int2* __restrict__ csr,
                          int ecnt) {
    int j = blockIdx.x * blockDim.x + threadIdx.x;
    if (j >= ecnt) return;
    int dst = ei[ecnt + j];
    int cm = ea[j * 3] * 100 + ea[j * 3 + 1] * 10 + ea[j * 3 + 2];
    int pos = atomicAdd(&cur[dst], 1);
    csr[pos] = make_int2(ei[j], cm);
}

// ---------------------------------------------------------------------------
// h += vn[batch]; optionally gsum[batch] += h (post-update)
// ---------------------------------------------------------------------------
__global__ void add_vn_k(float* __restrict__ h, const float* __restrict__ vn,
                         const int* __restrict__ batch,
                         float* __restrict__ gsum, int n, int dosum) {
    int idx = blockIdx.x * blockDim.x + threadIdx.x;
    if (idx >= n * 32) return;
    int node = idx >> 5;
    int c4 = (idx & 31) << 2;
    int g = batch[node];
    float4 hv = *(float4*)(h + idx * 4);
    float4 vv = *(const float4*)(vn + g * DD + c4);
    hv.x += vv.x; hv.y += vv.y; hv.z += vv.z; hv.w += vv.w;
    *(float4*)(h + idx * 4) = hv;
    if (dosum) {
        float* p = gsum + g * DD + c4;
        asm volatile("red.global.add.v4.f32 [%0], {%1,%2,%3,%4};"
                     :: "l"(p), "f"(hv.x), "f"(hv.y), "f"(hv.z), "f"(hv.w)
                     : "memory");
    }
}

// ---------------------------------------------------------------------------
// Edge gather (CSR, packed int2), 4x unrolled
// ---------------------------------------------------------------------------
__global__ void edge_csr_k(const int* __restrict__ off,
                           const int2* __restrict__ csr,
                           const float* __restrict__ cb,
                           const float* __restrict__ h,
                           const float* __restrict__ eps_p,
                           __nv_bfloat16* __restrict__ zhi,
                           __nv_bfloat16* __restrict__ zlo, int n) {
    int warp = (blockIdx.x * blockDim.x + threadIdx.x) >> 5;
    if (warp >= n) return;
    int lane = threadIdx.x & 31;
    int c4 = lane << 2;
    float4 acc = make_float4(0.f, 0.f, 0.f, 0.f);
    int beg = off[warp], end = off[warp + 1];
    const unsigned FULL = 0xffffffffu;
    for (int base = beg; base < end; base += 32) {
        int m = min(32, end - base);
        int s = 0, cm = 0;
        if (base + lane < end) {
            int2 e = csr[base + lane];
            s = e.x; cm = e.y;
        }
        int k = 0;
        for (; k + 4 <= m; k += 4) {
            int s0 = __shfl_sync(FULL, s, k),     c0 = __shfl_sync(FULL, cm, k);
            int s1 = __shfl_sync(FULL, s, k + 1), c1 = __shfl_sync(FULL, cm, k + 1);
            int s2 = __shfl_sync(FULL, s, k + 2), c2 = __shfl_sync(FULL, cm, k + 2);
            int s3 = __shfl_sync(FULL, s, k + 3), c3 = __shfl_sync(FULL, cm, k + 3);
            float4 h0 = *(const float4*)(h + (size_t)s0 * DD + c4);
            float4 e0 = *(const float4*)(cb + (size_t)c0 * DD + c4);
            float4 h1 = *(const float4*)(h + (size_t)s1 * DD + c4);
            float4 e1 = *(const float4*)(cb + (size_t)c1 * DD + c4);
            float4 h2 = *(const float4*)(h + (size_t)s2 * DD + c4);
            float4 e2 = *(const float4*)(cb + (size_t)c2 * DD + c4);
            float4 h3 = *(const float4*)(h + (size_t)s3 * DD + c4);
            float4 e3 = *(const float4*)(cb + (size_t)c3 * DD + c4);
            acc.x += fmaxf(h0.x + e0.x, 0.f) + fmaxf(h1.x + e1.x, 0.f)
                   + fmaxf(h2.x + e2.x, 0.f) + fmaxf(h3.x + e3.x, 0.f);
            acc.y += fmaxf(h0.y + e0.y, 0.f) + fmaxf(h1.y + e1.y, 0.f)
                   + fmaxf(h2.y + e2.y, 0.f) + fmaxf(h3.y + e3.y, 0.f);
            acc.z += fmaxf(h0.z + e0.z, 0.f) + fmaxf(h1.z + e1.z, 0.f)
                   + fmaxf(h2.z + e2.z, 0.f) + fmaxf(h3.z + e3.z, 0.f);
            acc.w += fmaxf(h0.w + e0.w, 0.f) + fmaxf(h1.w + e1.w, 0.f)
                   + fmaxf(h2.w + e2.w, 0.f) + fmaxf(h3.w + e3.w, 0.f);
        }
        for (; k < m; k++) {
            int ss = __shfl_sync(FULL, s, k);
            int cc = __shfl_sync(FULL, cm, k);
            float4 hv = *(const float4*)(h + (size_t)ss * DD + c4);
            float4 ev = *(const float4*)(cb + (size_t)cc * DD + c4);
            acc.x += fmaxf(hv.x + ev.x, 0.f);
            acc.y += fmaxf(hv.y + ev.y, 0.f);
            acc.z += fmaxf(hv.z + ev.z, 0.f);
            acc.w += fmaxf(hv.w + ev.w, 0.f);
        }
    }
    float al = 1.0f + *eps_p;
    float4 hv = *(const float4*)(h + (size_t)warp * DD + c4);
    unsigned short h0, h1, h2, h3, l0, l1, l2, l3;
    split_bf16(al * hv.x + acc.x, h0, l0);
    split_bf16(al * hv.y + acc.y, h1, l1);
    split_bf16(al * hv.z + acc.z, h2, l2);
    split_bf16(al * hv.w + acc.w, h3, l3);
    uint2 hp = make_uint2((uint32_t)h0 | ((uint32_t)h1 << 16),
                          (uint32_t)h2 | ((uint32_t)h3 << 16));
    uint2 lp = make_uint2((uint32_t)l0 | ((uint32_t)l1 << 16),
                          (uint32_t)l2 | ((uint32_t)l3 << 16));
    *(uint2*)(zhi + (size_t)warp * DD + c4) = hp;
    *(uint2*)(zlo + (size_t)warp * DD + c4) = lp;
}

// ---------------------------------------------------------------------------
// Unified GEMM with vn rider blocks, cp.async 2-stage pipeline, BK=32.
// Smem stride 40 halves (80B): ldmatrix rows hit banks 0,20,8,28,16,4,24,12
// -> conflict-free.
// ---------------------------------------------------------------------------
#define ASTR 40
#define STG_A_HI 0
#define STG_A_LO 10240
#define STG_B_HI 20480
#define STG_B_LO 25600
#define STG_SZ   30720
#define SM_TOT   61440

__global__ void __launch_bounds__(256)
gemm_uni_k(int gx0, int ny0, int M0,
           const __nv_bfloat16* __restrict__ A0hi,
           const __nv_bfloat16* __restrict__ A0lo,
           const __nv_bfloat16* __restrict__ B0hi,
           const __nv_bfloat16* __restrict__ B0lo,
           const float* __restrict__ lb0, const float* __restrict__ g0,
           const float* __restrict__ be0, const float* __restrict__ m0,
           const float* __restrict__ vv0,
           float* __restrict__ C0f,
           __nv_bfloat16* __restrict__ C0hi, __nv_bfloat16* __restrict__ C0lo,
           int ny1, int M1,
           const float* __restrict__ A1f, const float* __restrict__ A1f2,
           const __nv_bfloat16* __restrict__ A1hi,
           const __nv_bfloat16* __restrict__ A1lo,
           const __nv_bfloat16* __restrict__ B1hi,
           const __nv_bfloat16* __restrict__ B1lo,
           const float* __restrict__ lb1, const float* __restrict__ g1,
           const float* __restrict__ be1, const float* __restrict__ m1,
           const float* __restrict__ vv1,
           float* __restrict__ C1f,
           __nv_bfloat16* __restrict__ C1hi, __nv_bfloat16* __restrict__ C1lo,
           float4* __restrict__ zbuf, int zcnt4,
           int N, int K, int do_relu) {
    extern __shared__ char dsm[];
    __shared__ float s_sc[64], s_sb[64];

    int tid = threadIdx.x;
    int lane = tid & 31, wid = tid >> 5;

    int q = blockIdx.x;
    int part = 0, bx, by;
    if (q < gx0 * ny0) { bx = q / ny0; by = q % ny0; }
    else { part = 1; q -= gx0 * ny0; bx = q / ny1; by = q % ny1; }

    int M = part ? M1 : M0;
    const __nv_bfloat16* Ahi = part ? A1hi : A0hi;
    const __nv_bfloat16* Alo = part ? A1lo : A0lo;
    const __nv_bfloat16* Bh  = part ? B1hi : B0hi;
    const __nv_bfloat16* Bl  = part ? B1lo : B0lo;
    const float* lb = part ? lb1 : lb0;
    const float* gg = part ? g1 : g0;
    const float* bbp = part ? be1 : be0;
    const float* mmp = part ? m1 : m0;
    const float* vvp = part ? vv1 : vv0;
    float* Cf = part ? C1f : C0f;
    __nv_bfloat16* Chi = part ? C1hi : C0hi;
    __nv_bfloat16* Clo = part ? C1lo : C0lo;
    const float* Af  = part ? A1f  : (const float*)0;
    const float* Af2 = part ? A1f2 : (const float*)0;
    bool fp32A = (part && Af);

    int bm = bx * 128;
    int bn = by * 64;

    if (part == 1 && zbuf) {
        int rb = gridDim.x - gx0 * ny0;
        int rid = bx * ny1 + by;
        for (int i = rid * 256 + tid; i < zcnt4; i += rb * 256)
            zbuf[i] = make_float4(0.f, 0.f, 0.f, 0.f);
    }

    if (tid < 64) {
        int col = bn + tid;
        float s = gg[col] * rsqrtf(vvp[col] + 1e-5f);
        s_sc[tid] = s;
        s_sb[tid] = (lb[col] - mmp[col]) * s + bbp[col];
    }

    uint32_t smbase = cvta_s(dsm);
    int wm = (wid >> 1) * 32;
    int wn = (wid & 1) * 32;

    float acc[2][4][4];
#pragma unroll
    for (int a = 0; a < 2; a++)
#pragma unroll
        for (int b = 0; b < 4; b++)
#pragma unroll
            for (int qq = 0; qq < 4; qq++) acc[a][b][qq] = 0.f;

    int r8 = lane & 7, g = lane >> 3;
    int arow = wm + ((g & 1) << 3) + r8;
    int acolg = (g >> 1) << 3;
    int brow = wn + ((g >> 1) << 3) + r8;
    int bcolg = (g & 1) << 3;

    int nch = K >> 5;

    // ---- stage fill helpers
    auto issue_async = [&](int ch, int stg) {
        int cc = ch << 5;
        uint32_t sb = smbase + stg * STG_SZ;
#pragma unroll
        for (int it = 0; it < 2; it++) {
            int i = tid + it * 256;
            int row = i >> 2, c8 = (i & 3) << 3;
            int sz = (bm + row < M) ? 16 : 0;
            const __nv_bfloat16* sh = Ahi + (size_t)(bm + row) * K + cc + c8;
            const __nv_bfloat16* sl = Alo + (size_t)(bm + row) * K + cc + c8;
            uint32_t doff = (uint32_t)(row * ASTR + c8) * 2;
            CP_ASYNC16(sb + STG_A_HI + doff, sh, sz);
            CP_ASYNC16(sb + STG_A_LO + doff, sl, sz);
        }
        {
            int row = tid >> 2, c8 = (tid & 3) << 3;
            const __nv_bfloat16* sh = Bh + (size_t)(bn + row) * K + cc + c8;
            const __nv_bfloat16* sl = Bl + (size_t)(bn + row) * K + cc + c8;
            uint32_t doff = (uint32_t)(row * ASTR + c8) * 2;
            CP_ASYNC16(sb + STG_B_HI + doff, sh, 16);
            CP_ASYNC16(sb + STG_B_LO + doff, sl, 16);
        }
    };
    auto issue_sync = [&](int ch, int stg) {
        int cc = ch << 5;
        char* sb = dsm + stg * STG_SZ;
#pragma unroll
        for (int it = 0; it < 4; it++) {
            int i = tid + it * 256;
            int row = i >> 3, c4 = (i & 7) << 2;
            float4 v = make_float4(0.f, 0.f, 0.f, 0.f);
            if (bm + row < M) {
                v = *(const float4*)(Af + (size_t)(bm + row) * K + cc + c4);
                float4 w = *(const float4*)(Af2 + (size_t)(bm + row) * K + cc + c4);
                v.x += w.x; v.y += w.y; v.z += w.z; v.w += w.w;
            }
            unsigned short h0, h1, h2, h3, l0, l1, l2, l3;
            split_bf16(v.x, h0, l0); split_bf16(v.y, h1, l1);
            split_bf16(v.z, h2, l2); split_bf16(v.w, h3, l3);
            int off = (row * ASTR + c4) * 2;
            *(uint2*)(sb + STG_A_HI + off) = make_uint2(
                (uint32_t)h0 | ((uint32_t)h1 << 16),
                (uint32_t)h2 | ((uint32_t)h3 << 16));
            *(uint2*)(sb + STG_A_LO + off) = make_uint2(
                (uint32_t)l0 | ((uint32_t)l1 << 16),
                (uint32_t)l2 | ((uint32_t)l3 << 16));
        }
        {
            int row = tid >> 2, c8 = (tid & 3) << 3;
            uint4 vh = *(const uint4*)(Bh + (size_t)(bn + row) * K + cc + c8);
            uint4 vl = *(const uint4*)(Bl + (size_t)(bn + row) * K + cc + c8);
            int off = (row * ASTR + c8) * 2;
            *(uint4*)(sb + STG_B_HI + off) = vh;
            *(uint4*)(sb + STG_B_LO + off) = vl;
        }
    };

    // ---- prologue
    if (fp32A) issue_sync(0, 0);
    else       issue_async(0, 0);
    CP_COMMIT();

    for (int ch = 0; ch < nch; ch++) {
        if (ch + 1 < nch) {
            if (fp32A) issue_sync(ch + 1, (ch + 1) & 1);
            else       issue_async(ch + 1, (ch + 1) & 1);
        }
        CP_COMMIT();
        CP_WAIT1();
        __syncthreads();

        uint32_t sb = smbase + (ch & 1) * STG_SZ;
#pragma unroll
        for (int ks = 0; ks < 2; ks++) {
            int kk = ks << 4;
            uint32_t ah0, ah1, ah2, ah3, ah4, ah5, ah6, ah7;
            uint32_t am0, am1, am2, am3, am4, am5, am6, am7;
            uint32_t bh0, bh1, bh2, bh3, bh4, bh5, bh6, bh7;
            uint32_t bm0, bm1, bm2, bm3, bm4, bm5, bm6, bm7;
            {
                uint32_t ad0 = sb + STG_A_HI + ((arow) * ASTR + kk + acolg) * 2;
                uint32_t ad1 = sb + STG_A_HI + ((arow + 16) * ASTR + kk + acolg) * 2;
                LDSM_X4(ah0, ah1, ah2, ah3, ad0);
                LDSM_X4(ah4, ah5, ah6, ah7, ad1);
                LDSM_X4(am0, am1, am2, am3, ad0 + (STG_A_LO - STG_A_HI));
                LDSM_X4(am4, am5, am6, am7, ad1 + (STG_A_LO - STG_A_HI));
                uint32_t bd0 = sb + STG_B_HI + ((brow) * ASTR + kk + bcolg) * 2;
                uint32_t bd1 = sb + STG_B_HI + ((brow + 16) * ASTR + kk + bcolg) * 2;
                LDSM_X4(bh0, bh1, bh2, bh3, bd0);
                LDSM_X4(bh4, bh5, bh6, bh7, bd1);
                LDSM_X4(bm0, bm1, bm2, bm3, bd0 + (STG_B_LO - STG_B_HI));
                LDSM_X4(bm4, bm5, bm6, bm7, bd1 + (STG_B_LO - STG_B_HI));
            }
#define DO_NT(mt, nt, B0, B1, BL0, BL1, A0, A1, A2_, A3, AL0, AL1, AL2, AL3)    \
            MMA_BF16(acc[mt][nt][0], acc[mt][nt][1], acc[mt][nt][2],            \
                     acc[mt][nt][3], A0, A1, A2_, A3, B0, B1);                  \
            MMA_BF16(acc[mt][nt][0], acc[mt][nt][1], acc[mt][nt][2],            \
                     acc[mt][nt][3], A0, A1, A2_, A3, BL0, BL1);                \
            MMA_BF16(acc[mt][nt][0], acc[mt][nt][1], acc[mt][nt][2],            \
                     acc[mt][nt][3], AL0, AL1, AL2, AL3, B0, B1);
            DO_NT(0, 0, bh0, bh1, bm0, bm1, ah0, ah1, ah2, ah3, am0, am1, am2, am3)
            DO_NT(0, 1, bh2, bh3, bm2, bm3, ah0, ah1, ah2, ah3, am0, am1, am2, am3)
            DO_NT(0, 2, bh4, bh5, bm4, bm5, ah0, ah1, ah2, ah3, am0, am1, am2, am3)
            DO_NT(0, 3, bh6, bh7, bm6, bm7, ah0, ah1, ah2, ah3, am0, am1, am2, am3)
            DO_NT(1, 0, bh0, bh1, bm0, bm1, ah4, ah5, ah6, ah7, am4, am5, am6, am7)
            DO_NT(1, 1, bh2, bh3, bm2, bm3, ah4, ah5, ah6, ah7, am4, am5, am6, am7)
            DO_NT(1, 2, bh4, bh5, bm4, bm5, ah4, ah5, ah6, ah7, am4, am5, am6, am7)
            DO_NT(1, 3, bh6, bh7, bm6, bm7, ah4, ah5, ah6, ah7, am4, am5, am6, am7)
#undef DO_NT
        }
        __syncthreads();
    }

    int rq = lane >> 2, cq = (lane & 3) * 2;
    bool outBF = (Chi != (__nv_bfloat16*)0);
#pragma unroll
    for (int mt = 0; mt < 2; mt++) {
        int r0 = bm + wm + mt * 16 + rq;
#pragma unroll
        for (int nt = 0; nt < 4; nt++) {
            int c0 = wn + nt * 8 + cq;
            float s0 = s_sc[c0], s1 = s_sc[c0 + 1];
            float t0 = s_sb[c0], t1 = s_sb[c0 + 1];
            float v0 = acc[mt][nt][0] * s0 + t0;
            float v1 = acc[mt][nt][1] * s1 + t1;
            float v2 = acc[mt][nt][2] * s0 + t0;
            float v3 = acc[mt][nt][3] * s1 + t1;
            if (do_relu) {
                v0 = fmaxf(v0, 0.f); v1 = fmaxf(v1, 0.f);
                v2 = fmaxf(v2, 0.f); v3 = fmaxf(v3, 0.f);
            }
            if (outBF) {
                unsigned short h0, h1, h2, h3, l0, l1, l2, l3;
                split_bf16(v0, h0, l0); split_bf16(v1, h1, l1);
                split_bf16(v2, h2, l2); split_bf16(v3, h3, l3);
                if (r0 < M) {
                    *(uint32_t*)(Chi + (size_t)r0 * N + bn + c0) =
                        (uint32_t)h0 | ((uint32_t)h1 << 16);
                    *(uint32_t*)(Clo + (size_t)r0 * N + bn + c0) =
                        (uint32_t)l0 | ((uint32_t)l1 << 16);
                }
                if (r0 + 8 < M) {
                    *(uint32_t*)(Chi + (size_t)(r0 + 8) * N + bn + c0) =
                        (uint32_t)h2 | ((uint32_t)h3 << 16);
                    *(uint32_t*)(Clo + (size_t)(r0 + 8) * N + bn + c0) =
                        (uint32_t)l2 | ((uint32_t)l3 << 16);
                }
            } else {
                if (r0 < M)
                    *(float2*)(Cf + (size_t)r0 * N + bn + c0) = make_float2(v0, v1);
                if (r0 + 8 < M)
                    *(float2*)(Cf + (size_t)(r0 + 8) * N + bn + c0) = make_float2(v2, v3);
            }
        }
    }
}

// ---------------------------------------------------------------------------
// Host driver
// ---------------------------------------------------------------------------
extern "C" void kernel_launch(void* const* d_in, const int* in_sizes, int n_in,
                              void* d_out, int out_size) {
    const int*   x_atom  = (const int*)d_in[0];
    const int*   ei      = (const int*)d_in[1];
    const int*   ea      = (const int*)d_in[2];
    const int*   batch   = (const int*)d_in[3];
    const float* atomemb = (const float*)d_in[4];
    const float* vn0     = (const float*)d_in[5];
    const float* bond    = (const float*)d_in[6];
    const float* eps     = (const float*)d_in[7];
    const float* W1      = (const float*)d_in[8];
    const float* b1v     = (const float*)d_in[9];
    const float* bn1g    = (const float*)d_in[10];
    const float* bn1b    = (const float*)d_in[11];
    const float* bn1m    = (const float*)d_in[12];
    const float* bn1v    = (const float*)d_in[13];
    const float* W2      = (const float*)d_in[14];
    const float* b2v     = (const float*)d_in[15];
    const float* bng     = (const float*)d_in[16];
    const float* bnb     = (const float*)d_in[17];
    const float* bnm     = (const float*)d_in[18];
    const float* bnv     = (const float*)d_in[19];
    const float* vnW1    = (const float*)d_in[20];
    const float* vnb1    = (const float*)d_in[21];
    const float* vbn1g   = (const float*)d_in[22];
    const float* vbn1b   = (const float*)d_in[23];
    const float* vbn1m   = (const float*)d_in[24];
    const float* vbn1v   = (const float*)d_in[25];
    const float* vnW2    = (const float*)d_in[26];
    const float* vnb2    = (const float*)d_in[27];
    const float* vbn2g   = (const float*)d_in[28];
    const float* vbn2b   = (const float*)d_in[29];
    const float* vbn2m   = (const float*)d_in[30];
    const float* vbn2v   = (const float*)d_in[31];

    int n = in_sizes[3];
    int ecnt = in_sizes[1] / 2;

    float *h, *vn, *gsum, *cb;
    __nv_bfloat16 *zhi, *zlo, *thi, *tlo, *vthi, *vtlo, *Bhi, *Blo;
    int *cnt, *off, *cur;
    int2* csr;
    cudaGetSymbolAddress((void**)&h, g_h);
    cudaGetSymbolAddress((void**)&zhi, g_zhi);
    cudaGetSymbolAddress((void**)&zlo, g_zlo);
    cudaGetSymbolAddress((void**)&thi, g_thi);
    cudaGetSymbolAddress((void**)&tlo, g_tlo);
    cudaGetSymbolAddress((void**)&vn, g_vn);
    cudaGetSymbolAddress((void**)&gsum, g_gsum);
    cudaGetSymbolAddress((void**)&vthi, g_vthi);
    cudaGetSymbolAddress((void**)&vtlo, g_vtlo);
    cudaGetSymbolAddress((void**)&cb, g_cb);
    cudaGetSymbolAddress((void**)&cnt, g_cnt);
    cudaGetSymbolAddress((void**)&off, g_off);
    cudaGetSymbolAddress((void**)&cur, g_cur);
    cudaGetSymbolAddress((void**)&csr, g_csr);
    cudaGetSymbolAddress((void**)&Bhi, g_Bhi);
    cudaGetSymbolAddress((void**)&Blo, g_Blo);

    cudaFuncSetAttribute(gemm_uni_k, cudaFuncAttributeMaxDynamicSharedMemorySize,
                         SM_TOT);

    const int WSLOT = 32768;
    int gridND = (n * 32 + 255) / 256;

    int c1 = (10 * 32768 + 255) / 256;
    int c2 = c1 + (LL * 1000 * 32 + 255) / 256;
    int c3 = c2 + (n + 255) / 256;
    int c4b = c3 + (GG * 32 + 255) / 256;
    int c5 = c4b + gridND;
    int c6 = c5 + (GG * 32 + 255) / 256;
    fused_pre_k<<<c6, 256>>>(W1, W2, vnW1, vnW2, Bhi, Blo, bond, cb,
                             cnt, gsum, x_atom, atomemb, h, vn0, vn,
                             n, c1, c2, c3, c4b, c5);
    count_k<<<(ecnt / 4 + 255) / 256, 256>>>(ei, cnt, ecnt);
    scan_k<<<1, 1024>>>(cnt, off, cur, n, ecnt);
    scatter_k<<<(ecnt + 255) / 256, 256>>>(ei, ea, cur, csr, ecnt);

    int gridM = (n + 127) / 128;
    int gxv = GG / 128;
    for (int l = 0; l < LL; l++) {
        int hasVN = (l < LL - 1) ? 1 : 0;
        add_vn_k<<<gridND, 256>>>(h, vn, batch, gsum, n, hasVN);
        edge_csr_k<<<gridND, 256>>>(off, csr, cb + (size_t)l * 1000 * DD, h,
                                    eps + l, zhi, zlo, n);
        {
            int ny0 = 4, ny1 = 4;
            int grid = gridM * ny0 + (hasVN ? gxv * ny1 : 0);
            gemm_uni_k<<<grid, 256, SM_TOT>>>(
                gridM, ny0, n,
                zhi, zlo,
                Bhi + (size_t)l * WSLOT, Blo + (size_t)l * WSLOT,
                b1v + l * 256, bn1g + l * 256, bn1b + l * 256,
                bn1m + l * 256, bn1v + l * 256,
                nullptr, thi, tlo,
                ny1, hasVN ? GG : 0,
                vn, gsum, nullptr, nullptr,
                Bhi + (size_t)(6 + l) * WSLOT, Blo + (size_t)(6 + l) * WSLOT,
                vnb1 + l * 256, vbn1g + l * 256, vbn1b + l * 256,
                vbn1m + l * 256, vbn1v + l * 256,
                nullptr, vthi, vtlo,
                nullptr, 0,
                256, 128, 1);
        }
        {
            float* outp = (l == LL - 1) ? (float*)d_out : h;
            int ny0 = 2, ny1 = 2;
            int grid = gridM * ny0 + (hasVN ? gxv * ny1 : 0);
            gemm_uni_k<<<grid, 256, SM_TOT>>>(
                gridM, ny0, n,
                thi, tlo,
                Bhi + (size_t)(3 + l) * WSLOT, Blo + (size_t)(3 + l) * WSLOT,
                b2v + l * 128, bng + l * 128, bnb + l * 128,
                bnm + l * 128, bnv + l * 128,
                outp, nullptr, nullptr,
                ny1, hasVN ? GG : 0,
                nullptr, nullptr, vthi, vtlo,
                Bhi + (size_t)(8 + l) * WSLOT, Blo + (size_t)(8 + l) * WSLOT,
                vnb2 + l * 128, vbn2g + l * 128, vbn2b + l * 128,
                vbn2m + l * 128, vbn2v + l * 128,
                vn, nullptr, nullptr,
                (l == 0) ? (float4*)gsum : nullptr, GG * 32,
                128, 256, hasVN);
        }
    }
}

// round 9
// speedup vs baseline: 1.9027x; 1.0252x over previous
#include <cuda_runtime.h>
#include <cuda_bf16.h>
#include <cstdint>

#define MAXN 50000
#define MAXE 800000
#define GG   1024
#define DD   128
#define LL   3

// ---------------------------------------------------------------------------
// Static scratch
// ---------------------------------------------------------------------------
__device__ float g_h[MAXN * DD];
__device__ __nv_bfloat16 g_zhi[MAXN * DD];
__device__ __nv_bfloat16 g_zlo[MAXN * DD];
__device__ __nv_bfloat16 g_thi[MAXN * 2 * DD];
__device__ __nv_bfloat16 g_tlo[MAXN * 2 * DD];
__device__ float g_vn[GG * DD];
__device__ float g_gsum[GG * DD];
__device__ __nv_bfloat16 g_vthi[GG * 2 * DD];
__device__ __nv_bfloat16 g_vtlo[GG * 2 * DD];
__device__ float g_cb[LL * 1000 * DD];
__device__ int   g_cnt[MAXN];
__device__ int   g_off[MAXN + 1];
__device__ int   g_rank[MAXE];
__device__ int2  g_csr[MAXE];                  // packed {src, combo}
// Preconverted weights: B^T [N][K] bf16 hi/lo. 10 slots of 32768:
// W1 l0..2, W2 l0..2, vn1 l0..1, vn2 l0..1
__device__ __nv_bfloat16 g_Bhi[10 * 32768];
__device__ __nv_bfloat16 g_Blo[10 * 32768];

// ---------------------------------------------------------------------------
// PTX helpers
// ---------------------------------------------------------------------------
__device__ __forceinline__ uint32_t cvta_s(const void* p) {
    uint32_t a;
    asm("{ .reg .u64 t; cvta.to.shared.u64 t, %1; cvt.u32.u64 %0, t; }"
        : "=r"(a) : "l"(p));
    return a;
}
#define LDSM_X4(r0, r1, r2, r3, addr)                                          \
    asm volatile("ldmatrix.sync.aligned.m8n8.x4.shared.b16 {%0,%1,%2,%3}, [%4];"\
                 : "=r"(r0), "=r"(r1), "=r"(r2), "=r"(r3) : "r"(addr))
#define MMA_BF16(d0, d1, d2, d3, a0, a1, a2, a3, b0, b1)                       \
    asm volatile("mma.sync.aligned.m16n8k16.row.col.f32.bf16.bf16.f32 "        \
                 "{%0,%1,%2,%3}, {%4,%5,%6,%7}, {%8,%9}, {%0,%1,%2,%3};"       \
                 : "+f"(d0), "+f"(d1), "+f"(d2), "+f"(d3)                      \
                 : "r"(a0), "r"(a1), "r"(a2), "r"(a3), "r"(b0), "r"(b1))
#define CP_ASYNC16(dst, src, sz)                                               \
    asm volatile("cp.async.cg.shared.global [%0], [%1], 16, %2;"               \
                 :: "r"(dst), "l"(src), "r"(sz))
#define CP_COMMIT() asm volatile("cp.async.commit_group;" ::: "memory")
#define CP_WAIT1()  asm volatile("cp.async.wait_group 1;" ::: "memory")

__device__ __forceinline__ void split_bf16(float v, unsigned short& hi,
                                           unsigned short& lo) {
    __nv_bfloat16 h = __float2bfloat16_rn(v);
    hi = __bfloat16_as_ushort(h);
    lo = __bfloat16_as_ushort(__float2bfloat16_rn(v - __bfloat162float(h)));
}

// ---------------------------------------------------------------------------
// Mega-fused preprocessing
// ---------------------------------------------------------------------------
__global__ void fused_pre_k(
    const float* __restrict__ W1, const float* __restrict__ W2,
    const float* __restrict__ vnW1, const float* __restrict__ vnW2,
    __nv_bfloat16* __restrict__ Bhi, __nv_bfloat16* __restrict__ Blo,
    const float* __restrict__ bond, float* __restrict__ cb,
    int* __restrict__ cnt, float* __restrict__ gsum,
    const int* __restrict__ xa, const float* __restrict__ emb,
    float* __restrict__ h,
    const float* __restrict__ v0, float* __restrict__ vn,
    int n, int c1, int c2, int c3, int c4b, int c5) {
    int blk = blockIdx.x;
    int tid = threadIdx.x;
    if (blk < c1) {
        int idx = blk * 256 + tid;
        if (idx < 10 * 32768) {
            int slot = idx >> 15;
            int r = idx & 32767;
            const float* W;
            int Nd;
            if (slot < 3)      { W = W1 + (size_t)slot * 32768;         Nd = 256; }
            else if (slot < 6) { W = W2 + (size_t)(slot - 3) * 32768;   Nd = 128; }
            else if (slot < 8) { W = vnW1 + (size_t)(slot - 6) * 32768; Nd = 256; }
            else               { W = vnW2 + (size_t)(slot - 8) * 32768; Nd = 128; }
            int Kd = 32768 / Nd;
            int k = r / Nd, nn = r % Nd;
            unsigned short hi, lo;
            split_bf16(W[r], hi, lo);
            size_t o = (size_t)slot * 32768 + (size_t)nn * Kd + k;
            Bhi[o] = __ushort_as_bfloat16(hi);
            Blo[o] = __ushort_as_bfloat16(lo);
        }
    } else if (blk < c2) {
        int idx = (blk - c1) * 256 + tid;
        if (idx < LL * 1000 * 32) {
            int cc4 = (idx & 31) << 2;
            int i = (idx >> 5) % 1000;
            int l = (idx >> 5) / 1000;
            int f0 = i / 100, f1 = (i / 10) % 10, f2 = i % 10;
            float4 a = *(const float4*)(bond + ((size_t)(l * 3 + 0) * 10 + f0) * DD + cc4);
            float4 b = *(const float4*)(bond + ((size_t)(l * 3 + 1) * 10 + f1) * DD + cc4);
            float4 c = *(const float4*)(bond + ((size_t)(l * 3 + 2) * 10 + f2) * DD + cc4);
            float4 o;
            o.x = a.x + b.x + c.x; o.y = a.y + b.y + c.y;
            o.z = a.z + b.z + c.z; o.w = a.w + b.w + c.w;
            *(float4*)(cb + ((size_t)(l * 1000 + i)) * DD + cc4) = o;
        }
    } else if (blk < c3) {
        int i = (blk - c2) * 256 + tid;
        if (i < n) cnt[i] = 0;
    } else if (blk < c4b) {
        int i = (blk - c3) * 256 + tid;
        if (i < GG * 32)
            *(float4*)(gsum + i * 4) = make_float4(0.f, 0.f, 0.f, 0.f);
    } else if (blk < c5) {
        int idx = (blk - c4b) * 256 + tid;
        if (idx < n * 32) {
            int node = idx >> 5;
            int cc4 = (idx & 31) << 2;
            float4 s = make_float4(0.f, 0.f, 0.f, 0.f);
#pragma unroll
            for (int f = 0; f < 9; f++) {
                int v = xa[node * 9 + f];
                float4 e = *(const float4*)(emb + (f * 100 + v) * DD + cc4);
                s.x += e.x; s.y += e.y; s.z += e.z; s.w += e.w;
            }
            *(float4*)(h + node * DD + cc4) = s;
        }
    } else {
        int idx = (blk - c5) * 256 + tid;
        if (idx < GG * 32) {
            int cc4 = (idx & 31) << 2;
            *(float4*)(vn + idx * 4) = *(const float4*)(v0 + cc4);
        }
    }
}

// ---------------------------------------------------------------------------
// CSR build: count also records each edge's rank within its dst bucket.
// ---------------------------------------------------------------------------
__global__ void count_k(const int* __restrict__ ei, int* __restrict__ cnt,
                        int* __restrict__ rank, int ecnt) {
    int j = (blockIdx.x * blockDim.x + threadIdx.x) * 4;
    if (j + 3 < ecnt) {
        int4 d = *(const int4*)(ei + ecnt + j);
        rank[j + 0] = atomicAdd(&cnt[d.x], 1);
        rank[j + 1] = atomicAdd(&cnt[d.y], 1);
        rank[j + 2] = atomicAdd(&cnt[d.z], 1);
        rank[j + 3] = atomicAdd(&cnt[d.w], 1);
    } else {
        for (int q = j; q < ecnt; q++)
            rank[q] = atomicAdd(&cnt[ei[ecnt + q]], 1);
    }
}
__global__ void scan_k(const int* __restrict__ cnt, int* __restrict__ off,
                       int n, int ecnt) {
    __shared__ int part[1024];
    int t = threadIdx.x;
    int chunk = (n + 1023) >> 10;
    int beg = t * chunk;
    int end = min(beg + chunk, n);
    int s = 0;
    for (int i = beg; i < end; i++) s += cnt[i];
    part[t] = s;
    __syncthreads();
    for (int d = 1; d < 1024; d <<= 1) {
        int v = (t >= d) ? part[t - d] : 0;
        __syncthreads();
        if (t >= d) part[t] += v;
        __syncthreads();
    }
    int run = (t == 0) ? 0 : part[t - 1];
    for (int i = beg; i < end; i++) {
        off[i] = run;
        run += cnt[i];
    }
    if (t == 0) off[n] = ecnt;
}
__global__ void scatter_k(const int* __restrict__ ei, const int* __restrict__ ea,
                          const int* __restrict__ off, const int* __restrict__ rank,
                          int2* __restrict__ csr, int ecnt) {
    int j = blockIdx.x * blockDim.x + threadIdx.x;
    if (j >= ecnt) return;
    int dst = ei[ecnt + j];
    int cm = ea[j * 3] * 100 + ea[j * 3 + 1] * 10 + ea[j * 3 + 2];
    csr[off[dst] + rank[j]] = make_int2(ei[j], cm);
}

// ---------------------------------------------------------------------------
// h += vn[batch]; optionally gsum[batch] += h (post-update)
// ---------------------------------------------------------------------------
__global__ void add_vn_k(float* __restrict__ h, const float* __restrict__ vn,
                         const int* __restrict__ batch,
                         float* __restrict__ gsum, int n, int dosum) {
    int idx = blockIdx.x * blockDim.x + threadIdx.x;
    if (idx >= n * 32) return;
    int node = idx >> 5;
    int c4 = (idx & 31) << 2;
    int g = batch[node];
    float4 hv = *(float4*)(h + idx * 4);
    float4 vv = *(const float4*)(vn + g * DD + c4);
    hv.x += vv.x; hv.y += vv.y; hv.z += vv.z; hv.w += vv.w;
    *(float4*)(h + idx * 4) = hv;
    if (dosum) {
        float* p = gsum + g * DD + c4;
        asm volatile("red.global.add.v4.f32 [%0], {%1,%2,%3,%4};"
                     :: "l"(p), "f"(hv.x), "f"(hv.y), "f"(hv.z), "f"(hv.w)
                     : "memory");
    }
}

// ---------------------------------------------------------------------------
// Edge gather (CSR, packed int2), 4x unrolled
// ---------------------------------------------------------------------------
__global__ void edge_csr_k(const int* __restrict__ off,
                           const int2* __restrict__ csr,
                           const float* __restrict__ cb,
                           const float* __restrict__ h,
                           const float* __restrict__ eps_p,
                           __nv_bfloat16* __restrict__ zhi,
                           __nv_bfloat16* __restrict__ zlo, int n) {
    int warp = (blockIdx.x * blockDim.x + threadIdx.x) >> 5;
    if (warp >= n) return;
    int lane = threadIdx.x & 31;
    int c4 = lane << 2;
    float4 acc = make_float4(0.f, 0.f, 0.f, 0.f);
    int beg = off[warp], end = off[warp + 1];
    const unsigned FULL = 0xffffffffu;
    for (int base = beg; base < end; base += 32) {
        int m = min(32, end - base);
        int s = 0, cm = 0;
        if (base + lane < end) {
            int2 e = csr[base + lane];
            s = e.x; cm = e.y;
        }
        int k = 0;
        for (; k + 4 <= m; k += 4) {
            int s0 = __shfl_sync(FULL, s, k),     c0 = __shfl_sync(FULL, cm, k);
            int s1 = __shfl_sync(FULL, s, k + 1), c1 = __shfl_sync(FULL, cm, k + 1);
            int s2 = __shfl_sync(FULL, s, k + 2), c2 = __shfl_sync(FULL, cm, k + 2);
            int s3 = __shfl_sync(FULL, s, k + 3), c3 = __shfl_sync(FULL, cm, k + 3);
            float4 h0 = *(const float4*)(h + (size_t)s0 * DD + c4);
            float4 e0 = *(const float4*)(cb + (size_t)c0 * DD + c4);
            float4 h1 = *(const float4*)(h + (size_t)s1 * DD + c4);
            float4 e1 = *(const float4*)(cb + (size_t)c1 * DD + c4);
            float4 h2 = *(const float4*)(h + (size_t)s2 * DD + c4);
            float4 e2 = *(const float4*)(cb + (size_t)c2 * DD + c4);
            float4 h3 = *(const float4*)(h + (size_t)s3 * DD + c4);
            float4 e3 = *(const float4*)(cb + (size_t)c3 * DD + c4);
            acc.x += fmaxf(h0.x + e0.x, 0.f) + fmaxf(h1.x + e1.x, 0.f)
                   + fmaxf(h2.x + e2.x, 0.f) + fmaxf(h3.x + e3.x, 0.f);
            acc.y += fmaxf(h0.y + e0.y, 0.f) + fmaxf(h1.y + e1.y, 0.f)
                   + fmaxf(h2.y + e2.y, 0.f) + fmaxf(h3.y + e3.y, 0.f);
            acc.z += fmaxf(h0.z + e0.z, 0.f) + fmaxf(h1.z + e1.z, 0.f)
                   + fmaxf(h2.z + e2.z, 0.f) + fmaxf(h3.z + e3.z, 0.f);
            acc.w += fmaxf(h0.w + e0.w, 0.f) + fmaxf(h1.w + e1.w, 0.f)
                   + fmaxf(h2.w + e2.w, 0.f) + fmaxf(h3.w + e3.w, 0.f);
        }
        for (; k < m; k++) {
            int ss = __shfl_sync(FULL, s, k);
            int cc = __shfl_sync(FULL, cm, k);
            float4 hv = *(const float4*)(h + (size_t)ss * DD + c4);
            float4 ev = *(const float4*)(cb + (size_t)cc * DD + c4);
            acc.x += fmaxf(hv.x + ev.x, 0.f);
            acc.y += fmaxf(hv.y + ev.y, 0.f);
            acc.z += fmaxf(hv.z + ev.z, 0.f);
            acc.w += fmaxf(hv.w + ev.w, 0.f);
        }
    }
    float al = 1.0f + *eps_p;
    float4 hv = *(const float4*)(h + (size_t)warp * DD + c4);
    unsigned short h0, h1, h2, h3, l0, l1, l2, l3;
    split_bf16(al * hv.x + acc.x, h0, l0);
    split_bf16(al * hv.y + acc.y, h1, l1);
    split_bf16(al * hv.z + acc.z, h2, l2);
    split_bf16(al * hv.w + acc.w, h3, l3);
    uint2 hp = make_uint2((uint32_t)h0 | ((uint32_t)h1 << 16),
                          (uint32_t)h2 | ((uint32_t)h3 << 16));
    uint2 lp = make_uint2((uint32_t)l0 | ((uint32_t)l1 << 16),
                          (uint32_t)l2 | ((uint32_t)l3 << 16));
    *(uint2*)(zhi + (size_t)warp * DD + c4) = hp;
    *(uint2*)(zlo + (size_t)warp * DD + c4) = lp;
}

// ---------------------------------------------------------------------------
// Persistent unified GEMM with vn rider tiles, cp.async 2-stage, BK=32.
// grid = min(total_tiles, 296); each CTA loops over tiles.
// ---------------------------------------------------------------------------
#define ASTR 40
#define STG_A_HI 0
#define STG_A_LO 10240
#define STG_B_HI 20480
#define STG_B_LO 25600
#define STG_SZ   30720
#define SM_TOT   61440

__global__ void __launch_bounds__(256, 2)
gemm_uni_k(int gx0, int ny0, int M0,
           const __nv_bfloat16* __restrict__ A0hi,
           const __nv_bfloat16* __restrict__ A0lo,
           const __nv_bfloat16* __restrict__ B0hi,
           const __nv_bfloat16* __restrict__ B0lo,
           const float* __restrict__ lb0, const float* __restrict__ g0,
           const float* __restrict__ be0, const float* __restrict__ m0,
           const float* __restrict__ vv0,
           float* __restrict__ C0f,
           __nv_bfloat16* __restrict__ C0hi, __nv_bfloat16* __restrict__ C0lo,
           int gx1, int ny1, int M1,
           const float* __restrict__ A1f, const float* __restrict__ A1f2,
           const __nv_bfloat16* __restrict__ A1hi,
           const __nv_bfloat16* __restrict__ A1lo,
           const __nv_bfloat16* __restrict__ B1hi,
           const __nv_bfloat16* __restrict__ B1lo,
           const float* __restrict__ lb1, const float* __restrict__ g1,
           const float* __restrict__ be1, const float* __restrict__ m1,
           const float* __restrict__ vv1,
           float* __restrict__ C1f,
           __nv_bfloat16* __restrict__ C1hi, __nv_bfloat16* __restrict__ C1lo,
           float4* __restrict__ zbuf, int zcnt4,
           int N, int K, int do_relu) {
    extern __shared__ char dsm[];
    __shared__ float s_sc[64], s_sb[64];

    int tid = threadIdx.x;
    int lane = tid & 31, wid = tid >> 5;
    uint32_t smbase = cvta_s(dsm);

    // cooperative zero of next-layer gsum (independent of GEMM data)
    if (zbuf) {
        for (int i = blockIdx.x * 256 + tid; i < zcnt4; i += gridDim.x * 256)
            zbuf[i] = make_float4(0.f, 0.f, 0.f, 0.f);
    }

    int ntile0 = gx0 * ny0;
    int total = ntile0 + gx1 * ny1;

    int wm = (wid >> 1) * 32;
    int wn = (wid & 1) * 32;
    int r8 = lane & 7, g = lane >> 3;
    int acolg = (g >> 1) << 3;
    int bcolg = (g & 1) << 3;
    int nch = K >> 5;

    for (int tile = blockIdx.x; tile < total; tile += gridDim.x) {
        int part = 0, bx, by;
        int q = tile;
        if (q < ntile0) { bx = q / ny0; by = q % ny0; }
        else { part = 1; q -= ntile0; bx = q / ny1; by = q % ny1; }

        int M = part ? M1 : M0;
        const __nv_bfloat16* Ahi = part ? A1hi : A0hi;
        const __nv_bfloat16* Alo = part ? A1lo : A0lo;
        const __nv_bfloat16* Bh  = part ? B1hi : B0hi;
        const __nv_bfloat16* Bl  = part ? B1lo : B0lo;
        const float* lb = part ? lb1 : lb0;
        const float* gg = part ? g1 : g0;
        const float* bbp = part ? be1 : be0;
        const float* mmp = part ? m1 : m0;
        const float* vvp = part ? vv1 : vv0;
        float* Cf = part ? C1f : C0f;
        __nv_bfloat16* Chi = part ? C1hi : C0hi;
        __nv_bfloat16* Clo = part ? C1lo : C0lo;
        const float* Af  = part ? A1f  : (const float*)0;
        const float* Af2 = part ? A1f2 : (const float*)0;
        bool fp32A = (part && Af);

        int bm = bx * 128;
        int bn = by * 64;

        __syncthreads();   // guard s_sc reuse vs previous tile's epilogue
        if (tid < 64) {
            int col = bn + tid;
            float s = gg[col] * rsqrtf(vvp[col] + 1e-5f);
            s_sc[tid] = s;
            s_sb[tid] = (lb[col] - mmp[col]) * s + bbp[col];
        }

        float acc[2][4][4];
#pragma unroll
        for (int a = 0; a < 2; a++)
#pragma unroll
            for (int b = 0; b < 4; b++)
#pragma unroll
                for (int qq = 0; qq < 4; qq++) acc[a][b][qq] = 0.f;

        int arow = wm + ((g & 1) << 3) + r8;
        int brow = wn + ((g >> 1) << 3) + r8;

        // stage fill helpers
        auto issue_async = [&](int ch, int stg) {
            int cc = ch << 5;
            uint32_t sb = smbase + stg * STG_SZ;
#pragma unroll
            for (int it = 0; it < 2; it++) {
                int i = tid + it * 256;
                int row = i >> 2, c8 = (i & 3) << 3;
                int sz = (bm + row < M) ? 16 : 0;
                const __nv_bfloat16* sh = Ahi + (size_t)(bm + row) * K + cc + c8;
                const __nv_bfloat16* sl = Alo + (size_t)(bm + row) * K + cc + c8;
                uint32_t doff = (uint32_t)(row * ASTR + c8) * 2;
                CP_ASYNC16(sb + STG_A_HI + doff, sh, sz);
                CP_ASYNC16(sb + STG_A_LO + doff, sl, sz);
            }
            {
                int row = tid >> 2, c8 = (tid & 3) << 3;
                const __nv_bfloat16* sh = Bh + (size_t)(bn + row) * K + cc + c8;
                const __nv_bfloat16* sl = Bl + (size_t)(bn + row) * K + cc + c8;
                uint32_t doff = (uint32_t)(row * ASTR + c8) * 2;
                CP_ASYNC16(sb + STG_B_HI + doff, sh, 16);
                CP_ASYNC16(sb + STG_B_LO + doff, sl, 16);
            }
        };
        auto issue_sync = [&](int ch, int stg) {
            int cc = ch << 5;
            char* sb = dsm + stg * STG_SZ;
#pragma unroll
            for (int it = 0; it < 4; it++) {
                int i = tid + it * 256;
                int row = i >> 3, c4 = (i & 7) << 2;
                float4 v = make_float4(0.f, 0.f, 0.f, 0.f);
                if (bm + row < M) {
                    v = *(const float4*)(Af + (size_t)(bm + row) * K + cc + c4);
                    float4 w = *(const float4*)(Af2 + (size_t)(bm + row) * K + cc + c4);
                    v.x += w.x; v.y += w.y; v.z += w.z; v.w += w.w;
                }
                unsigned short h0, h1, h2, h3, l0, l1, l2, l3;
                split_bf16(v.x, h0, l0); split_bf16(v.y, h1, l1);
                split_bf16(v.z, h2, l2); split_bf16(v.w, h3, l3);
                int off = (row * ASTR + c4) * 2;
                *(uint2*)(sb + STG_A_HI + off) = make_uint2(
                    (uint32_t)h0 | ((uint32_t)h1 << 16),
                    (uint32_t)h2 | ((uint32_t)h3 << 16));
                *(uint2*)(sb + STG_A_LO + off) = make_uint2(
                    (uint32_t)l0 | ((uint32_t)l1 << 16),
                    (uint32_t)l2 | ((uint32_t)l3 << 16));
            }
            {
                int row = tid >> 2, c8 = (tid & 3) << 3;
                uint4 vh = *(const uint4*)(Bh + (size_t)(bn + row) * K + cc + c8);
                uint4 vl = *(const uint4*)(Bl + (size_t)(bn + row) * K + cc + c8);
                int off = (row * ASTR + c8) * 2;
                *(uint4*)(sb + STG_B_HI + off) = vh;
                *(uint4*)(sb + STG_B_LO + off) = vl;
            }
        };

        if (fp32A) issue_sync(0, 0);
        else       issue_async(0, 0);
        CP_COMMIT();

        for (int ch = 0; ch < nch; ch++) {
            if (ch + 1 < nch) {
                if (fp32A) issue_sync(ch + 1, (ch + 1) & 1);
                else       issue_async(ch + 1, (ch + 1) & 1);
            }
            CP_COMMIT();
            CP_WAIT1();
            __syncthreads();

            uint32_t sb = smbase + (ch & 1) * STG_SZ;
#pragma unroll
            for (int ks = 0; ks < 2; ks++) {
                int kk = ks << 4;
                uint32_t ah0, ah1, ah2, ah3, ah4, ah5, ah6, ah7;
                uint32_t am0, am1, am2, am3, am4, am5, am6, am7;
                uint32_t bh0, bh1, bh2, bh3, bh4, bh5, bh6, bh7;
                uint32_t bm0, bm1, bm2, bm3, bm4, bm5, bm6, bm7;
                {
                    uint32_t ad0 = sb + STG_A_HI + ((arow) * ASTR + kk + acolg) * 2;
                    uint32_t ad1 = sb + STG_A_HI + ((arow + 16) * ASTR + kk + acolg) * 2;
                    LDSM_X4(ah0, ah1, ah2, ah3, ad0);
                    LDSM_X4(ah4, ah5, ah6, ah7, ad1);
                    LDSM_X4(am0, am1, am2, am3, ad0 + (STG_A_LO - STG_A_HI));
                    LDSM_X4(am4, am5, am6, am7, ad1 + (STG_A_LO - STG_A_HI));
                    uint32_t bd0 = sb + STG_B_HI + ((brow) * ASTR + kk + bcolg) * 2;
                    uint32_t bd1 = sb + STG_B_HI + ((brow + 16) * ASTR + kk + bcolg) * 2;
                    LDSM_X4(bh0, bh1, bh2, bh3, bd0);
                    LDSM_X4(bh4, bh5, bh6, bh7, bd1);
                    LDSM_X4(bm0, bm1, bm2, bm3, bd0 + (STG_B_LO - STG_B_HI));
                    LDSM_X4(bm4, bm5, bm6, bm7, bd1 + (STG_B_LO - STG_B_HI));
                }
#define DO_NT(mt, nt, B0, B1, BL0, BL1, A0, A1, A2_, A3, AL0, AL1, AL2, AL3)    \
                MMA_BF16(acc[mt][nt][0], acc[mt][nt][1], acc[mt][nt][2],        \
                         acc[mt][nt][3], A0, A1, A2_, A3, B0, B1);              \
                MMA_BF16(acc[mt][nt][0], acc[mt][nt][1], acc[mt][nt][2],        \
                         acc[mt][nt][3], A0, A1, A2_, A3, BL0, BL1);            \
                MMA_BF16(acc[mt][nt][0], acc[mt][nt][1], acc[mt][nt][2],        \
                         acc[mt][nt][3], AL0, AL1, AL2, AL3, B0, B1);
                DO_NT(0, 0, bh0, bh1, bm0, bm1, ah0, ah1, ah2, ah3, am0, am1, am2, am3)
                DO_NT(0, 1, bh2, bh3, bm2, bm3, ah0, ah1, ah2, ah3, am0, am1, am2, am3)
                DO_NT(0, 2, bh4, bh5, bm4, bm5, ah0, ah1, ah2, ah3, am0, am1, am2, am3)
                DO_NT(0, 3, bh6, bh7, bm6, bm7, ah0, ah1, ah2, ah3, am0, am1, am2, am3)
                DO_NT(1, 0, bh0, bh1, bm0, bm1, ah4, ah5, ah6, ah7, am4, am5, am6, am7)
                DO_NT(1, 1, bh2, bh3, bm2, bm3, ah4, ah5, ah6, ah7, am4, am5, am6, am7)
                DO_NT(1, 2, bh4, bh5, bm4, bm5, ah4, ah5, ah6, ah7, am4, am5, am6, am7)
                DO_NT(1, 3, bh6, bh7, bm6, bm7, ah4, ah5, ah6, ah7, am4, am5, am6, am7)
#undef DO_NT
            }
            __syncthreads();
        }

        // ---- epilogue
        int rq = lane >> 2, cq = (lane & 3) * 2;
        bool outBF = (Chi != (__nv_bfloat16*)0);
#pragma unroll
        for (int mt = 0; mt < 2; mt++) {
            int r0 = bm + wm + mt * 16 + rq;
#pragma unroll
            for (int nt = 0; nt < 4; nt++) {
                int c0 = wn + nt * 8 + cq;
                float s0 = s_sc[c0], s1 = s_sc[c0 + 1];
                float t0 = s_sb[c0], t1 = s_sb[c0 + 1];
                float v0 = acc[mt][nt][0] * s0 + t0;
                float v1 = acc[mt][nt][1] * s1 + t1;
                float v2 = acc[mt][nt][2] * s0 + t0;
                float v3 = acc[mt][nt][3] * s1 + t1;
                if (do_relu) {
                    v0 = fmaxf(v0, 0.f); v1 = fmaxf(v1, 0.f);
                    v2 = fmaxf(v2, 0.f); v3 = fmaxf(v3, 0.f);
                }
                if (outBF) {
                    unsigned short h0, h1, h2, h3, l0, l1, l2, l3;
                    split_bf16(v0, h0, l0); split_bf16(v1, h1, l1);
                    split_bf16(v2, h2, l2); split_bf16(v3, h3, l3);
                    if (r0 < M) {
                        *(uint32_t*)(Chi + (size_t)r0 * N + bn + c0) =
                            (uint32_t)h0 | ((uint32_t)h1 << 16);
                        *(uint32_t*)(Clo + (size_t)r0 * N + bn + c0) =
                            (uint32_t)l0 | ((uint32_t)l1 << 16);
                    }
                    if (r0 + 8 < M) {
                        *(uint32_t*)(Chi + (size_t)(r0 + 8) * N + bn + c0) =
                            (uint32_t)h2 | ((uint32_t)h3 << 16);
                        *(uint32_t*)(Clo + (size_t)(r0 + 8) * N + bn + c0) =
                            (uint32_t)l2 | ((uint32_t)l3 << 16);
                    }
                } else {
                    if (r0 < M)
                        *(float2*)(Cf + (size_t)r0 * N + bn + c0) = make_float2(v0, v1);
                    if (r0 + 8 < M)
                        *(float2*)(Cf + (size_t)(r0 + 8) * N + bn + c0) = make_float2(v2, v3);
                }
            }
        }
    }
}

// ---------------------------------------------------------------------------
// Host driver
// ---------------------------------------------------------------------------
extern "C" void kernel_launch(void* const* d_in, const int* in_sizes, int n_in,
                              void* d_out, int out_size) {
    const int*   x_atom  = (const int*)d_in[0];
    const int*   ei      = (const int*)d_in[1];
    const int*   ea      = (const int*)d_in[2];
    const int*   batch   = (const int*)d_in[3];
    const float* atomemb = (const float*)d_in[4];
    const float* vn0     = (const float*)d_in[5];
    const float* bond    = (const float*)d_in[6];
    const float* eps     = (const float*)d_in[7];
    const float* W1      = (const float*)d_in[8];
    const float* b1v     = (const float*)d_in[9];
    const float* bn1g    = (const float*)d_in[10];
    const float* bn1b    = (const float*)d_in[11];
    const float* bn1m    = (const float*)d_in[12];
    const float* bn1v    = (const float*)d_in[13];
    const float* W2      = (const float*)d_in[14];
    const float* b2v     = (const float*)d_in[15];
    const float* bng     = (const float*)d_in[16];
    const float* bnb     = (const float*)d_in[17];
    const float* bnm     = (const float*)d_in[18];
    const float* bnv     = (const float*)d_in[19];
    const float* vnW1    = (const float*)d_in[20];
    const float* vnb1    = (const float*)d_in[21];
    const float* vbn1g   = (const float*)d_in[22];
    const float* vbn1b   = (const float*)d_in[23];
    const float* vbn1m   = (const float*)d_in[24];
    const float* vbn1v   = (const float*)d_in[25];
    const float* vnW2    = (const float*)d_in[26];
    const float* vnb2    = (const float*)d_in[27];
    const float* vbn2g   = (const float*)d_in[28];
    const float* vbn2b   = (const float*)d_in[29];
    const float* vbn2m   = (const float*)d_in[30];
    const float* vbn2v   = (const float*)d_in[31];

    int n = in_sizes[3];
    int ecnt = in_sizes[1] / 2;

    float *h, *vn, *gsum, *cb;
    __nv_bfloat16 *zhi, *zlo, *thi, *tlo, *vthi, *vtlo, *Bhi, *Blo;
    int *cnt, *off, *rank;
    int2* csr;
    cudaGetSymbolAddress((void**)&h, g_h);
    cudaGetSymbolAddress((void**)&zhi, g_zhi);
    cudaGetSymbolAddress((void**)&zlo, g_zlo);
    cudaGetSymbolAddress((void**)&thi, g_thi);
    cudaGetSymbolAddress((void**)&tlo, g_tlo);
    cudaGetSymbolAddress((void**)&vn, g_vn);
    cudaGetSymbolAddress((void**)&gsum, g_gsum);
    cudaGetSymbolAddress((void**)&vthi, g_vthi);
    cudaGetSymbolAddress((void**)&vtlo, g_vtlo);
    cudaGetSymbolAddress((void**)&cb, g_cb);
    cudaGetSymbolAddress((void**)&cnt, g_cnt);
    cudaGetSymbolAddress((void**)&off, g_off);
    cudaGetSymbolAddress((void**)&rank, g_rank);
    cudaGetSymbolAddress((void**)&csr, g_csr);
    cudaGetSymbolAddress((void**)&Bhi, g_Bhi);
    cudaGetSymbolAddress((void**)&Blo, g_Blo);

    cudaFuncSetAttribute(gemm_uni_k, cudaFuncAttributeMaxDynamicSharedMemorySize,
                         SM_TOT);

    const int WSLOT = 32768;
    int gridND = (n * 32 + 255) / 256;

    int c1 = (10 * 32768 + 255) / 256;
    int c2 = c1 + (LL * 1000 * 32 + 255) / 256;
    int c3 = c2 + (n + 255) / 256;
    int c4b = c3 + (GG * 32 + 255) / 256;
    int c5 = c4b + gridND;
    int c6 = c5 + (GG * 32 + 255) / 256;
    fused_pre_k<<<c6, 256>>>(W1, W2, vnW1, vnW2, Bhi, Blo, bond, cb,
                             cnt, gsum, x_atom, atomemb, h, vn0, vn,
                             n, c1, c2, c3, c4b, c5);
    count_k<<<(ecnt / 4 + 255) / 256, 256>>>(ei, cnt, rank, ecnt);
    scan_k<<<1, 1024>>>(cnt, off, n, ecnt);
    scatter_k<<<(ecnt + 255) / 256, 256>>>(ei, ea, off, rank, csr, ecnt);

    int gridM = (n + 127) / 128;
    int gxv = GG / 128;
    const int PERSIST = 296;   // 148 SMs x 2 CTAs
    for (int l = 0; l < LL; l++) {
        int hasVN = (l < LL - 1) ? 1 : 0;
        add_vn_k<<<gridND, 256>>>(h, vn, batch, gsum, n, hasVN);
        edge_csr_k<<<gridND, 256>>>(off, csr, cb + (size_t)l * 1000 * DD, h,
                                    eps + l, zhi, zlo, n);
        {
            int ny0 = 4, ny1 = 4;
            int gx1 = hasVN ? gxv : 0;
            int total = gridM * ny0 + gx1 * ny1;
            int grid = total < PERSIST ? total : PERSIST;
            gemm_uni_k<<<grid, 256, SM_TOT>>>(
                gridM, ny0, n,
                zhi, zlo,
                Bhi + (size_t)l * WSLOT, Blo + (size_t)l * WSLOT,
                b1v + l * 256, bn1g + l * 256, bn1b + l * 256,
                bn1m + l * 256, bn1v + l * 256,
                nullptr, thi, tlo,
                gx1, ny1, hasVN ? GG : 0,
                vn, gsum, nullptr, nullptr,
                Bhi + (size_t)(6 + l) * WSLOT, Blo + (size_t)(6 + l) * WSLOT,
                vnb1 + l * 256, vbn1g + l * 256, vbn1b + l * 256,
                vbn1m + l * 256, vbn1v + l * 256,
                nullptr, vthi, vtlo,
                nullptr, 0,
                256, 128, 1);
        }
        {
            float* outp = (l == LL - 1) ? (float*)d_out : h;
            int ny0 = 2, ny1 = 2;
            int gx1 = hasVN ? gxv : 0;
            int total = gridM * ny0 + gx1 * ny1;
            int grid = total < PERSIST ? total : PERSIST;
            gemm_uni_k<<<grid, 256, SM_TOT>>>(
                gridM, ny0, n,
                thi, tlo,
                Bhi + (size_t)(3 + l) * WSLOT, Blo + (size_t)(3 + l) * WSLOT,
                b2v + l * 128, bng + l * 128, bnb + l * 128,
                bnm + l * 128, bnv + l * 128,
                outp, nullptr, nullptr,
                gx1, ny1, hasVN ? GG : 0,
                nullptr, nullptr, vthi, vtlo,
                Bhi + (size_t)(8 + l) * WSLOT, Blo + (size_t)(8 + l) * WSLOT,
                vnb2 + l * 128, vbn2g + l * 128, vbn2b + l * 128,
                vbn2m + l * 128, vbn2v + l * 128,
                vn, nullptr, nullptr,
                (l == 0) ? (float4*)gsum : nullptr, GG * 32,
                128, 256, hasVN);
        }
    }
}